// round 13
// baseline (speedup 1.0000x reference)
#include <cuda_runtime.h>
#include <math.h>
#include <stdint.h>

#define BB 4
#define SS 4096
#define HH 2048
#define RR 64
#define K1 (HH * 7)      // 14336
#define N1 1024
#define N2 512
#define N3 256
#define NSPLIT 32
#define SCHUNK (SS / NSPLIT)   // 128 s rows per block
#define SUB 32                 // s rows per smem sub-tile
#define KSPLIT1 448            // layer-1 split-K chunks (Kchunk=32)

// ---------------- scratch (__device__ globals; no allocations) ----------------
__device__ float g_p1[NSPLIT * BB * HH];
__device__ float g_p2[NSPLIT * BB * HH];
__device__ float g_p3[NSPLIT * BB * HH];
__device__ float g_p4[NSPLIT * BB * HH];
__device__ float g_pmx[NSPLIT * BB * HH];
__device__ float g_pmn[NSPLIT * BB * HH];
__device__ float g_rn2[8 * BB * SS];   // rownorm sum-of-squares partials (8 h-slices)
__device__ float g_feats[BB * K1];
__device__ float g_partial[KSPLIT1 * BB * N1];
__device__ float g_z1[BB * N1];
__device__ float g_z2[BB * N2];
__device__ float g_h1[BB * N1];
__device__ float g_h2[BB * N2];
__device__ float g_h3[BB * N3];
__device__ float g_U[BB * HH * RR];   // [b][h][r]  (tf32-rounded)
__device__ float g_V[BB * RR * HH];   // [b][r][h]  (tf32-rounded)
__device__ float g_hsb[(size_t)BB * SS * HH];  // hs @ base (general fallback only)
__device__ int   g_flag;              // 1 = base_transform is identity

// ---------------- tf32 mma helpers ----------------
__device__ __forceinline__ float tf32r(float x) {
    uint32_t u;
    asm("cvt.rna.tf32.f32 %0, %1;" : "=r"(u) : "f"(x));
    return __uint_as_float(u);
}
__device__ __forceinline__ void mma_tf32(float* c,
        uint32_t a0, uint32_t a1, uint32_t a2, uint32_t a3,
        uint32_t b0, uint32_t b1) {
    asm volatile(
        "mma.sync.aligned.m16n8k8.row.col.f32.tf32.tf32.f32 "
        "{%0,%1,%2,%3}, {%4,%5,%6,%7}, {%8,%9}, {%0,%1,%2,%3};"
        : "+f"(c[0]), "+f"(c[1]), "+f"(c[2]), "+f"(c[3])
        : "r"(a0), "r"(a1), "r"(a2), "r"(a3), "r"(b0), "r"(b1));
}

// ---------------- moments + rownorm, fused via smem tiles ----------------
__global__ __launch_bounds__(256) void k_moments(const float* __restrict__ hs) {
    __shared__ float tile[SUB][260];
    int h0 = blockIdx.x * 256;
    int b  = blockIdx.y;
    int sp = blockIdx.z;
    int tid = threadIdx.x;
    int warp = tid >> 5, lane = tid & 31;
    const float* base = hs + ((size_t)b * SS + (size_t)sp * SCHUNK) * HH + h0;

    float s1 = 0.f, s2 = 0.f, s3 = 0.f, s4 = 0.f;
    float mx = -1e30f, mn = 1e30f;

    float4 pf[8];
#pragma unroll
    for (int j = 0; j < 8; j++) {
        int lin = tid + j * 256;
        int r = lin >> 6, c = (lin & 63) << 2;
        pf[j] = *reinterpret_cast<const float4*>(base + (size_t)r * HH + c);
    }

#pragma unroll 1
    for (int st = 0; st < 4; st++) {
        if (st) __syncthreads();
#pragma unroll
        for (int j = 0; j < 8; j++) {
            int lin = tid + j * 256;
            int r = lin >> 6, c = (lin & 63) << 2;
            *reinterpret_cast<float4*>(&tile[r][c]) = pf[j];
        }
        __syncthreads();
        if (st < 3) {
#pragma unroll
            for (int j = 0; j < 8; j++) {
                int lin = tid + j * 256;
                int r = lin >> 6, c = (lin & 63) << 2;
                pf[j] = *reinterpret_cast<const float4*>(
                    base + (size_t)((st + 1) * SUB + r) * HH + c);
            }
        }
#pragma unroll
        for (int s = 0; s < SUB; s++) {
            float x  = tile[s][tid];
            float x2 = x * x;
            s1 += x; s2 += x2; s3 += x2 * x; s4 += x2 * x2;
            mx = fmaxf(mx, x); mn = fminf(mn, x);
        }
#pragma unroll
        for (int i = 0; i < 4; i++) {
            int r = warp * 4 + i;
            float4 a  = *reinterpret_cast<const float4*>(&tile[r][lane * 4]);
            float4 bq = *reinterpret_cast<const float4*>(&tile[r][lane * 4 + 128]);
            float v = (a.x * a.x + a.y * a.y) + (a.z * a.z + a.w * a.w)
                    + (bq.x * bq.x + bq.y * bq.y) + (bq.z * bq.z + bq.w * bq.w);
#pragma unroll
            for (int o = 16; o > 0; o >>= 1) v += __shfl_xor_sync(0xffffffffu, v, o);
            if (lane == 0)
                g_rn2[blockIdx.x * (BB * SS) + b * SS + sp * SCHUNK + st * SUB + r] = v;
        }
    }
    int idx = (sp * BB + b) * HH + h0 + tid;
    g_p1[idx] = s1; g_p2[idx] = s2; g_p3[idx] = s3; g_p4[idx] = s4;
    g_pmx[idx] = mx; g_pmn[idx] = mn;
    if (blockIdx.x == 0 && blockIdx.y == 0 && blockIdx.z == 0 && tid == 0)
        g_flag = 1;
}

// combine chunk partials -> features
__global__ void k_combine() {
    int h = blockIdx.x * 256 + threadIdx.x;
    int b = blockIdx.y;
    float s1 = 0.f, s2 = 0.f, s3 = 0.f, s4 = 0.f;
    float mx = -1e30f, mn = 1e30f;
#pragma unroll
    for (int sp = 0; sp < NSPLIT; sp++) {
        int idx = (sp * BB + b) * HH + h;
        s1 += g_p1[idx]; s2 += g_p2[idx]; s3 += g_p3[idx]; s4 += g_p4[idx];
        mx = fmaxf(mx, g_pmx[idx]); mn = fminf(mn, g_pmn[idx]);
    }
    float n  = (float)SS;
    float mu = s1 / n;
    float e2 = s2 / n;
    float e3 = s3 / n;
    float e4 = s4 / n;
    float varu = (s2 - n * mu * mu) / (n - 1.f);
    if (varu < 0.f) varu = 0.f;
    float sd  = sqrtf(varu);
    float m3  = e3 - 3.f * mu * e2 + 2.f * mu * mu * mu;
    float m4  = e4 - 4.f * mu * e3 + 6.f * mu * mu * e2 - 3.f * mu * mu * mu * mu;
    float skew = m3 / (sd * sd * sd + 1e-8f);
    float kurt = m4 / (varu * varu + 1e-8f) - 3.f;
    float* f = g_feats + (size_t)b * K1;
    f[0 * HH + h] = mu;
    f[1 * HH + h] = sd;
    f[3 * HH + h] = mx;
    f[4 * HH + h] = mn;
    f[5 * HH + h] = skew;
    f[6 * HH + h] = kurt;
}

// mean of row norms per batch -> broadcast into feats slot 2
__global__ void k_nrm() {
    int b = blockIdx.x;
    float acc = 0.f;
    for (int i = threadIdx.x; i < SS; i += 256) {
        float v = 0.f;
#pragma unroll
        for (int hsl = 0; hsl < 8; hsl++) v += g_rn2[hsl * (BB * SS) + b * SS + i];
        acc += sqrtf(v);
    }
    __shared__ float sh[256];
    __shared__ float nrm;
    sh[threadIdx.x] = acc; __syncthreads();
    for (int o = 128; o > 0; o >>= 1) {
        if (threadIdx.x < o) sh[threadIdx.x] += sh[threadIdx.x + o];
        __syncthreads();
    }
    if (threadIdx.x == 0) nrm = sh[0] / (float)SS;
    __syncthreads();
    for (int h = threadIdx.x; h < HH; h += 256)
        g_feats[(size_t)b * K1 + 2 * HH + h] = nrm;
}

// ---------------- layer-1 GEMM: float4 over n, Kchunk=32, 448 blocks ----------------
__global__ __launch_bounds__(256) void k_gemm1(const float* __restrict__ W,
        const float* __restrict__ X, float* __restrict__ partial) {
    __shared__ float xs[BB][32];
    int tid = threadIdx.x;
    int k0 = blockIdx.x * 32;
    if (tid < BB * 32)
        xs[tid >> 5][tid & 31] = X[(size_t)(tid >> 5) * K1 + k0 + (tid & 31)];
    __syncthreads();
    int n4 = tid * 4;
    float4 acc[BB];
#pragma unroll
    for (int bq = 0; bq < BB; bq++) acc[bq] = make_float4(0.f, 0.f, 0.f, 0.f);
    const float* Wp = W + (size_t)k0 * N1 + n4;
#pragma unroll 8
    for (int kk = 0; kk < 32; kk++) {
        float4 w = *reinterpret_cast<const float4*>(Wp + (size_t)kk * N1);
#pragma unroll
        for (int bq = 0; bq < BB; bq++) {
            float h = xs[bq][kk];
            acc[bq].x += h * w.x; acc[bq].y += h * w.y;
            acc[bq].z += h * w.z; acc[bq].w += h * w.w;
        }
    }
    int p = blockIdx.x * BB;
#pragma unroll
    for (int bq = 0; bq < BB; bq++)
        *reinterpret_cast<float4*>(partial + (size_t)(p + bq) * N1 + n4) = acc[bq];
}

// ---------------- small-M GEMM (M=4) with split-K (layers 2,3) ----------------
__global__ void k_gemm_sk(const float* __restrict__ W, const float* __restrict__ X,
                          float* __restrict__ partial, int K, int N, int Kchunk) {
    __shared__ float xs[BB][128];
    int n  = blockIdx.x * 256 + threadIdx.x;
    int k0 = blockIdx.y * Kchunk;
    for (int b = 0; b < BB; b++)
        for (int i = threadIdx.x; i < Kchunk; i += 256)
            xs[b][i] = X[(size_t)b * K + k0 + i];
    __syncthreads();
    if (n >= N) return;
    float a0 = 0.f, a1 = 0.f, a2 = 0.f, a3 = 0.f;
    const float* Wp = W + (size_t)k0 * N + n;
#pragma unroll 8
    for (int kk = 0; kk < Kchunk; kk++) {
        float w = Wp[(size_t)kk * N];
        a0 += xs[0][kk] * w; a1 += xs[1][kk] * w;
        a2 += xs[2][kk] * w; a3 += xs[3][kk] * w;
    }
    int p = blockIdx.y * BB;
    partial[(size_t)(p + 0) * N + n] = a0;
    partial[(size_t)(p + 1) * N + n] = a1;
    partial[(size_t)(p + 2) * N + n] = a2;
    partial[(size_t)(p + 3) * N + n] = a3;
}

__global__ void k_reduce_bias(const float* __restrict__ partial, const float* __restrict__ bias,
                              float* __restrict__ out, int N, int ksplit, int do_relu) {
    int i = blockIdx.x * 256 + threadIdx.x;
    if (i >= BB * N) return;
    int b = i / N, n = i % N;
    float a = bias[n];
#pragma unroll 8
    for (int ks = 0; ks < ksplit; ks++)
        a += partial[(size_t)(ks * BB + b) * N + n];
    if (do_relu) a = fmaxf(a, 0.f);
    out[i] = a;
}

// LayerNorm (population var, eps=1e-5) + ReLU
__global__ void k_ln_relu(const float* __restrict__ z, const float* __restrict__ g,
                          const float* __restrict__ beta, float* __restrict__ out, int N) {
    int b = blockIdx.x;
    const float* zr = z + (size_t)b * N;
    float s = 0.f, s2 = 0.f;
    for (int i = threadIdx.x; i < N; i += 256) { float x = zr[i]; s += x; s2 += x * x; }
    __shared__ float sha[256];
    __shared__ float shb[256];
    __shared__ float s_mean, s_rstd;
    sha[threadIdx.x] = s; shb[threadIdx.x] = s2; __syncthreads();
    for (int o = 128; o > 0; o >>= 1) {
        if (threadIdx.x < o) { sha[threadIdx.x] += sha[threadIdx.x + o]; shb[threadIdx.x] += shb[threadIdx.x + o]; }
        __syncthreads();
    }
    if (threadIdx.x == 0) {
        float mean = sha[0] / (float)N;
        float var  = shb[0] / (float)N - mean * mean;
        s_mean = mean;
        s_rstd = rsqrtf(var + 1e-5f);
    }
    __syncthreads();
    float mean = s_mean, rstd = s_rstd;
    for (int i = threadIdx.x; i < N; i += 256)
        out[(size_t)b * N + i] = fmaxf((zr[i] - mean) * rstd * g[i] + beta[i], 0.f);
}

// U = (h3 @ Wu + bu)*su ; V = (h3 @ Wv + bv)*sv. float4 over n, tf32-rounded on store.
__global__ __launch_bounds__(256) void k_uv(const float* __restrict__ Wu,
        const float* __restrict__ bu, const float* __restrict__ Wv,
        const float* __restrict__ bv, const float* __restrict__ su,
        const float* __restrict__ sv) {
    const int NU = HH * RR;
    int isv = blockIdx.y;
    const float* W    = isv ? Wv : Wu;
    const float* bias = isv ? bv : bu;
    float scale       = isv ? sv[0] : su[0];
    float* outp       = isv ? g_V : g_U;
    __shared__ float hsh[BB][N3];
    for (int i = threadIdx.x; i < BB * N3; i += 256)
        hsh[i / N3][i % N3] = g_h3[i];
    __syncthreads();
    int n = (blockIdx.x * 256 + threadIdx.x) * 4;
    float4 acc[BB];
#pragma unroll
    for (int bq = 0; bq < BB; bq++) acc[bq] = make_float4(0.f, 0.f, 0.f, 0.f);
    const float* Wp = W + n;
#pragma unroll 8
    for (int k = 0; k < N3; k++) {
        float4 w = *reinterpret_cast<const float4*>(Wp + (size_t)k * NU);
#pragma unroll
        for (int bq = 0; bq < BB; bq++) {
            float h = hsh[bq][k];
            acc[bq].x += h * w.x; acc[bq].y += h * w.y;
            acc[bq].z += h * w.z; acc[bq].w += h * w.w;
        }
    }
    float4 bb4 = *reinterpret_cast<const float4*>(bias + n);
#pragma unroll
    for (int bq = 0; bq < BB; bq++) {
        float4 o;
        o.x = tf32r((acc[bq].x + bb4.x) * scale);
        o.y = tf32r((acc[bq].y + bb4.y) * scale);
        o.z = tf32r((acc[bq].z + bb4.z) * scale);
        o.w = tf32r((acc[bq].w + bb4.w) * scale);
        *reinterpret_cast<float4*>(outp + (size_t)bq * NU + n) = o;
    }
}

// is base_transform == I ? (float4)
__global__ void k_idcheck(const float* __restrict__ base) {
    int i4 = blockIdx.x * 256 + threadIdx.x;
    int e0 = i4 * 4;
    int r = e0 >> 11, c0 = e0 & 2047;
    float4 x = *reinterpret_cast<const float4*>(base + e0);
    float4 e;
    e.x = (r == c0 + 0) ? 1.f : 0.f;
    e.y = (r == c0 + 1) ? 1.f : 0.f;
    e.z = (r == c0 + 2) ? 1.f : 0.f;
    e.w = (r == c0 + 3) ? 1.f : 0.f;
    if (x.x != e.x || x.y != e.y || x.z != e.z || x.w != e.w) g_flag = 0;
}

// fallback: g_hsb = hs @ base (only when base != I; early-exits otherwise). 8 k-tiles/block.
__global__ void k_basegemm(const float* __restrict__ hs, const float* __restrict__ base) {
    if (g_flag) return;
    __shared__ float As2[64][17];
    __shared__ float Bs2[16][64];
    int b   = blockIdx.z;
    int s0  = blockIdx.y * 64;
    int tid = threadIdx.x, tx = tid % 16, ty = tid / 16;
    const float* A = hs + ((size_t)b * SS + s0) * HH;
    for (int kt = 0; kt < 8; kt++) {
        int k0t = (blockIdx.x * 8 + kt) * 64;
        float acc[4][4] = {};
        for (int h0 = 0; h0 < HH; h0 += 16) {
#pragma unroll
            for (int j = 0; j < 4; j++) {
                int idx = tid + j * 256, r = idx / 16, c = idx % 16;
                As2[r][c] = A[(size_t)r * HH + h0 + c];
            }
#pragma unroll
            for (int j = 0; j < 4; j++) {
                int idx = tid + j * 256, r = idx / 64, c = idx % 64;
                Bs2[r][c] = base[(size_t)(h0 + r) * HH + k0t + c];
            }
            __syncthreads();
#pragma unroll
            for (int kk = 0; kk < 16; kk++) {
                float af[4], bf[4];
#pragma unroll
                for (int i = 0; i < 4; i++) af[i] = As2[ty * 4 + i][kk];
#pragma unroll
                for (int j = 0; j < 4; j++) bf[j] = Bs2[kk][tx * 4 + j];
#pragma unroll
                for (int i = 0; i < 4; i++)
#pragma unroll
                    for (int j = 0; j < 4; j++) acc[i][j] += af[i] * bf[j];
            }
            __syncthreads();
        }
        float* Op = g_hsb + ((size_t)b * SS + s0) * HH + k0t;
#pragma unroll
        for (int i = 0; i < 4; i++) {
            float4 v = make_float4(acc[i][0], acc[i][1], acc[i][2], acc[i][3]);
            *reinterpret_cast<float4*>(Op + (size_t)(ty * 4 + i) * HH + tx * 4) = v;
        }
    }
}

// ---------------- fused: T = hs@U in smem, then out = rw*src + cw*T@V ----------------
// grid (SS/64, BB), block 256 (8 warps). Phase 1: T(64x64) via tf32 MMA -> smem Ts.
// Phase 2: loop 32 V-tiles (64x64) across full H; epilogue blends with src.
__global__ __launch_bounds__(256, 2) void k_TF(const float* __restrict__ hs,
                                               const float* __restrict__ rw_p,
                                               float* __restrict__ out) {
    __shared__ float pool[4352 + 4608];
    float (*Ts)[68] = reinterpret_cast<float(*)[68]>(pool);                 // 64x68
    float (*As)[36] = reinterpret_cast<float(*)[36]>(pool + 4352);         // 64x36
    float (*Us)[72] = reinterpret_cast<float(*)[72]>(pool + 4352 + 2304);  // 32x72
    float (*Vs)[72] = reinterpret_cast<float(*)[72]>(pool + 4352);         // 64x72 (reuse)

    int b   = blockIdx.y;
    int s0  = blockIdx.x * 64;
    int tid = threadIdx.x;
    int warp = tid >> 5, lane = tid & 31;
    int gid = lane >> 2, tig = lane & 3;
    int wm = warp & 3, wn = warp >> 2;
    const float* A = hs  + ((size_t)b * SS + s0) * HH;
    const float* U = g_U + (size_t)b * HH * RR;

    // ---- phase 1: T = hs_tile @ U ----
    int laR[2], laC[2], luR[2], luC[2];
#pragma unroll
    for (int j = 0; j < 2; j++) {
        int lin = tid + j * 256;
        laR[j] = lin >> 3;  laC[j] = (lin & 7)  << 2;   // A: 64 x 32
        luR[j] = lin >> 4;  luC[j] = (lin & 15) << 2;   // U: 32 x 64
    }
    float4 fa[2], fu[2];
#pragma unroll
    for (int j = 0; j < 2; j++) {
        fa[j] = *reinterpret_cast<const float4*>(A + (size_t)laR[j] * HH + laC[j]);
        fu[j] = *reinterpret_cast<const float4*>(U + (size_t)luR[j] * RR + luC[j]);
    }

    float acc1[4][4] = {};
    for (int h0 = 0; h0 < HH; h0 += 32) {
        if (h0) __syncthreads();
#pragma unroll
        for (int j = 0; j < 2; j++) {
            float* pA = &As[laR[j]][laC[j]];
            pA[0] = tf32r(fa[j].x); pA[1] = tf32r(fa[j].y);
            pA[2] = tf32r(fa[j].z); pA[3] = tf32r(fa[j].w);
            *reinterpret_cast<float2*>(&Us[luR[j]][luC[j]])     = make_float2(fu[j].x, fu[j].y);
            *reinterpret_cast<float2*>(&Us[luR[j]][luC[j] + 2]) = make_float2(fu[j].z, fu[j].w);
        }
        __syncthreads();
        if (h0 + 32 < HH) {
#pragma unroll
            for (int j = 0; j < 2; j++) {
                fa[j] = *reinterpret_cast<const float4*>(A + (size_t)laR[j] * HH + h0 + 32 + laC[j]);
                fu[j] = *reinterpret_cast<const float4*>(U + (size_t)(h0 + 32 + luR[j]) * RR + luC[j]);
            }
        }
#pragma unroll
        for (int ks = 0; ks < 4; ks++) {
            int kk = ks * 8;
            uint32_t a0 = __float_as_uint(As[wm * 16 + gid    ][kk + tig]);
            uint32_t a1 = __float_as_uint(As[wm * 16 + gid + 8][kk + tig]);
            uint32_t a2 = __float_as_uint(As[wm * 16 + gid    ][kk + tig + 4]);
            uint32_t a3 = __float_as_uint(As[wm * 16 + gid + 8][kk + tig + 4]);
#pragma unroll
            for (int nt = 0; nt < 4; nt++) {
                int nc = wn * 32 + nt * 8 + gid;
                uint32_t b0 = __float_as_uint(Us[kk + tig    ][nc]);
                uint32_t b1 = __float_as_uint(Us[kk + tig + 4][nc]);
                mma_tf32(acc1[nt], a0, a1, a2, a3, b0, b1);
            }
        }
    }
    __syncthreads();   // done with As/Us region before Ts/Vs phase
    // store T to smem, tf32-rounded
#pragma unroll
    for (int nt = 0; nt < 4; nt++) {
        int c = wn * 32 + nt * 8 + 2 * tig;
        Ts[wm * 16 + gid    ][c]     = tf32r(acc1[nt][0]);
        Ts[wm * 16 + gid    ][c + 1] = tf32r(acc1[nt][1]);
        Ts[wm * 16 + gid + 8][c]     = tf32r(acc1[nt][2]);
        Ts[wm * 16 + gid + 8][c + 1] = tf32r(acc1[nt][3]);
    }
    __syncthreads();

    // ---- phase 2: out = rw*src + cw*T@V over full H ----
    float rw = rw_p[0];
    float cw = 1.f - rw;
    const float* src = g_flag ? hs : (const float*)g_hsb;
    const float* Vg = g_V + (size_t)b * RR * HH;

    float4 afr[8];
#pragma unroll
    for (int ks = 0; ks < 8; ks++) {
        int kk = ks * 8;
        afr[ks].x = Ts[wm * 16 + gid    ][kk + tig];
        afr[ks].y = Ts[wm * 16 + gid + 8][kk + tig];
        afr[ks].z = Ts[wm * 16 + gid    ][kk + tig + 4];
        afr[ks].w = Ts[wm * 16 + gid + 8][kk + tig + 4];
    }

#pragma unroll 1
    for (int kt = 0; kt < HH / 64; kt++) {
        int k0 = kt * 64;
        __syncthreads();   // previous Vs reads done
#pragma unroll
        for (int j = 0; j < 4; j++) {
            int lin = tid + j * 256;
            int r = lin >> 4, c = (lin & 15) << 2;
            *reinterpret_cast<float4*>(&Vs[r][c]) =
                *reinterpret_cast<const float4*>(Vg + (size_t)r * HH + k0 + c);
        }
        __syncthreads();
        float acc[4][4] = {};
#pragma unroll
        for (int ks = 0; ks < 8; ks++) {
            int kk = ks * 8;
            uint32_t a0 = __float_as_uint(afr[ks].x);
            uint32_t a1 = __float_as_uint(afr[ks].y);
            uint32_t a2 = __float_as_uint(afr[ks].z);
            uint32_t a3 = __float_as_uint(afr[ks].w);
#pragma unroll
            for (int nt = 0; nt < 4; nt++) {
                int nc = wn * 32 + nt * 8 + gid;
                uint32_t b0 = __float_as_uint(Vs[kk + tig    ][nc]);
                uint32_t b1 = __float_as_uint(Vs[kk + tig + 4][nc]);
                mma_tf32(acc[nt], a0, a1, a2, a3, b0, b1);
            }
        }
        size_t rowA = ((size_t)b * SS + s0 + wm * 16 + gid) * HH + k0 + wn * 32;
        size_t rowB = rowA + (size_t)8 * HH;
#pragma unroll
        for (int nt = 0; nt < 4; nt++) {
            int c = nt * 8 + 2 * tig;
            float2 xa = *reinterpret_cast<const float2*>(src + rowA + c);
            float2 xb = *reinterpret_cast<const float2*>(src + rowB + c);
            float2 oa = make_float2(rw * xa.x + cw * acc[nt][0], rw * xa.y + cw * acc[nt][1]);
            float2 ob = make_float2(rw * xb.x + cw * acc[nt][2], rw * xb.y + cw * acc[nt][3]);
            *reinterpret_cast<float2*>(out + rowA + c) = oa;
            *reinterpret_cast<float2*>(out + rowB + c) = ob;
        }
    }
}

// ---------------- launch ----------------
extern "C" void kernel_launch(void* const* d_in, const int* in_sizes, int n_in,
                              void* d_out, int out_size) {
    const float* hs  = (const float*)d_in[0];
    const float* W1  = (const float*)d_in[1];
    const float* b1  = (const float*)d_in[2];
    const float* g1  = (const float*)d_in[3];
    const float* be1 = (const float*)d_in[4];
    const float* W2  = (const float*)d_in[5];
    const float* b2  = (const float*)d_in[6];
    const float* g2  = (const float*)d_in[7];
    const float* be2 = (const float*)d_in[8];
    const float* W3  = (const float*)d_in[9];
    const float* b3  = (const float*)d_in[10];
    const float* Wu  = (const float*)d_in[11];
    const float* bu  = (const float*)d_in[12];
    const float* Wv  = (const float*)d_in[13];
    const float* bv  = (const float*)d_in[14];
    const float* su  = (const float*)d_in[15];
    const float* sv  = (const float*)d_in[16];
    const float* rw  = (const float*)d_in[17];
    const float* base= (const float*)d_in[18];
    float* out = (float*)d_out;

    float *p_feats, *p_part, *p_z1, *p_z2, *p_h1, *p_h2, *p_h3;
    cudaGetSymbolAddress((void**)&p_feats, g_feats);
    cudaGetSymbolAddress((void**)&p_part,  g_partial);
    cudaGetSymbolAddress((void**)&p_z1,    g_z1);
    cudaGetSymbolAddress((void**)&p_z2,    g_z2);
    cudaGetSymbolAddress((void**)&p_h1,    g_h1);
    cudaGetSymbolAddress((void**)&p_h2,    g_h2);
    cudaGetSymbolAddress((void**)&p_h3,    g_h3);

    k_moments<<<dim3(HH / 256, BB, NSPLIT), 256>>>(hs);
    k_combine<<<dim3(HH / 256, BB), 256>>>();
    k_nrm<<<BB, 256>>>();

    // layer 1: [4,14336] @ [14336,1024], Kchunk=32 -> 448 blocks
    k_gemm1<<<KSPLIT1, 256>>>(W1, p_feats, p_part);
    k_reduce_bias<<<(BB * N1 + 255) / 256, 256>>>(p_part, b1, p_z1, N1, KSPLIT1, 0);
    k_ln_relu<<<BB, 256>>>(p_z1, g1, be1, p_h1, N1);
    // layer 2: [4,1024] @ [1024,512]
    k_gemm_sk<<<dim3(N2 / 256, 8), 256>>>(W2, p_h1, p_part, N1, N2, 128);
    k_reduce_bias<<<(BB * N2 + 255) / 256, 256>>>(p_part, b2, p_z2, N2, 8, 0);
    k_ln_relu<<<BB, 256>>>(p_z2, g2, be2, p_h2, N2);
    // layer 3: [4,512] @ [512,256] + relu
    k_gemm_sk<<<dim3(1, 4), 256>>>(W3, p_h2, p_part, N2, N3, 128);
    k_reduce_bias<<<(BB * N3 + 255) / 256, 256>>>(p_part, b3, p_h3, N3, 4, 1);

    k_uv<<<dim3(HH * RR / 1024, 2), 256>>>(Wu, bu, Wv, bv, su, sv);
    k_idcheck<<<(HH * HH / 4) / 256, 256>>>(base);
    k_basegemm<<<dim3(HH / 512, SS / 64, BB), 256>>>(hs, base);
    k_TF<<<dim3(SS / 64, BB), 256>>>(hs, rw, out);
}

// round 14
// speedup vs baseline: 1.0943x; 1.0943x over previous
#include <cuda_runtime.h>
#include <math.h>
#include <stdint.h>

#define BB 4
#define SS 4096
#define HH 2048
#define RR 64
#define K1 (HH * 7)      // 14336
#define N1 1024
#define N2 512
#define N3 256
#define NSPLIT 32
#define SCHUNK (SS / NSPLIT)   // 128 s rows per block
#define SUB 32                 // s rows per smem sub-tile
#define KSPLIT1 224            // layer-1 split-K chunks (Kchunk=64)

// ---------------- scratch (__device__ globals; no allocations) ----------------
__device__ float g_p1[NSPLIT * BB * HH];
__device__ float g_p2[NSPLIT * BB * HH];
__device__ float g_p3[NSPLIT * BB * HH];
__device__ float g_p4[NSPLIT * BB * HH];
__device__ float g_pmx[NSPLIT * BB * HH];
__device__ float g_pmn[NSPLIT * BB * HH];
__device__ float g_rn2[8 * BB * SS];   // rownorm sum-of-squares partials (8 h-slices)
__device__ float g_feats[BB * K1];
__device__ float g_partial[KSPLIT1 * BB * N1];
__device__ float g_z1[BB * N1];
__device__ float g_z2[BB * N2];
__device__ float g_h1[BB * N1];
__device__ float g_h2[BB * N2];
__device__ float g_U[BB * HH * RR];   // [b][h][r]  (tf32-rounded)
__device__ float g_V[BB * RR * HH];   // [b][r][h]  (tf32-rounded)
__device__ float g_T[BB * SS * RR];   // hs @ U     (tf32-rounded)
__device__ float g_hsb[(size_t)BB * SS * HH];  // hs @ base (general fallback only)
__device__ int   g_flag;              // 1 = base_transform is identity

// ---------------- tf32 mma helpers ----------------
__device__ __forceinline__ float tf32r(float x) {
    uint32_t u;
    asm("cvt.rna.tf32.f32 %0, %1;" : "=r"(u) : "f"(x));
    return __uint_as_float(u);
}
__device__ __forceinline__ void mma_tf32(float* c,
        uint32_t a0, uint32_t a1, uint32_t a2, uint32_t a3,
        uint32_t b0, uint32_t b1) {
    asm volatile(
        "mma.sync.aligned.m16n8k8.row.col.f32.tf32.tf32.f32 "
        "{%0,%1,%2,%3}, {%4,%5,%6,%7}, {%8,%9}, {%0,%1,%2,%3};"
        : "+f"(c[0]), "+f"(c[1]), "+f"(c[2]), "+f"(c[3])
        : "r"(a0), "r"(a1), "r"(a2), "r"(a3), "r"(b0), "r"(b1));
}

// ---------------- moments + rownorm, fused via smem tiles ----------------
__global__ __launch_bounds__(256) void k_moments(const float* __restrict__ hs) {
    __shared__ float tile[SUB][260];
    int h0 = blockIdx.x * 256;
    int b  = blockIdx.y;
    int sp = blockIdx.z;
    int tid = threadIdx.x;
    int warp = tid >> 5, lane = tid & 31;
    const float* base = hs + ((size_t)b * SS + (size_t)sp * SCHUNK) * HH + h0;

    float s1 = 0.f, s2 = 0.f, s3 = 0.f, s4 = 0.f;
    float mx = -1e30f, mn = 1e30f;

    float4 pf[8];
#pragma unroll
    for (int j = 0; j < 8; j++) {
        int lin = tid + j * 256;
        int r = lin >> 6, c = (lin & 63) << 2;
        pf[j] = *reinterpret_cast<const float4*>(base + (size_t)r * HH + c);
    }

#pragma unroll 1
    for (int st = 0; st < 4; st++) {
        if (st) __syncthreads();
#pragma unroll
        for (int j = 0; j < 8; j++) {
            int lin = tid + j * 256;
            int r = lin >> 6, c = (lin & 63) << 2;
            *reinterpret_cast<float4*>(&tile[r][c]) = pf[j];
        }
        __syncthreads();
        if (st < 3) {
#pragma unroll
            for (int j = 0; j < 8; j++) {
                int lin = tid + j * 256;
                int r = lin >> 6, c = (lin & 63) << 2;
                pf[j] = *reinterpret_cast<const float4*>(
                    base + (size_t)((st + 1) * SUB + r) * HH + c);
            }
        }
#pragma unroll
        for (int s = 0; s < SUB; s++) {
            float x  = tile[s][tid];
            float x2 = x * x;
            s1 += x; s2 += x2; s3 += x2 * x; s4 += x2 * x2;
            mx = fmaxf(mx, x); mn = fminf(mn, x);
        }
#pragma unroll
        for (int i = 0; i < 4; i++) {
            int r = warp * 4 + i;
            float4 a  = *reinterpret_cast<const float4*>(&tile[r][lane * 4]);
            float4 bq = *reinterpret_cast<const float4*>(&tile[r][lane * 4 + 128]);
            float v = (a.x * a.x + a.y * a.y) + (a.z * a.z + a.w * a.w)
                    + (bq.x * bq.x + bq.y * bq.y) + (bq.z * bq.z + bq.w * bq.w);
#pragma unroll
            for (int o = 16; o > 0; o >>= 1) v += __shfl_xor_sync(0xffffffffu, v, o);
            if (lane == 0)
                g_rn2[blockIdx.x * (BB * SS) + b * SS + sp * SCHUNK + st * SUB + r] = v;
        }
    }
    int idx = (sp * BB + b) * HH + h0 + tid;
    g_p1[idx] = s1; g_p2[idx] = s2; g_p3[idx] = s3; g_p4[idx] = s4;
    g_pmx[idx] = mx; g_pmn[idx] = mn;
    if (blockIdx.x == 0 && blockIdx.y == 0 && blockIdx.z == 0 && tid == 0)
        g_flag = 1;   // reset identity flag; checked by k_gemm1 (later in stream)
}

// combine chunk partials -> features; blockIdx.x==8 lane does the rownorm mean
__global__ void k_combine_nrm() {
    int b = blockIdx.y;
    if (blockIdx.x == 8) {
        // mean of row norms per batch -> broadcast into feats slot 2
        float acc = 0.f;
        for (int i = threadIdx.x; i < SS; i += 256) {
            float v = 0.f;
#pragma unroll
            for (int hsl = 0; hsl < 8; hsl++) v += g_rn2[hsl * (BB * SS) + b * SS + i];
            acc += sqrtf(v);
        }
        __shared__ float sh[256];
        __shared__ float nrm;
        sh[threadIdx.x] = acc; __syncthreads();
        for (int o = 128; o > 0; o >>= 1) {
            if (threadIdx.x < o) sh[threadIdx.x] += sh[threadIdx.x + o];
            __syncthreads();
        }
        if (threadIdx.x == 0) nrm = sh[0] / (float)SS;
        __syncthreads();
        for (int h = threadIdx.x; h < HH; h += 256)
            g_feats[(size_t)b * K1 + 2 * HH + h] = nrm;
        return;
    }
    int h = blockIdx.x * 256 + threadIdx.x;
    float s1 = 0.f, s2 = 0.f, s3 = 0.f, s4 = 0.f;
    float mx = -1e30f, mn = 1e30f;
#pragma unroll
    for (int sp = 0; sp < NSPLIT; sp++) {
        int idx = (sp * BB + b) * HH + h;
        s1 += g_p1[idx]; s2 += g_p2[idx]; s3 += g_p3[idx]; s4 += g_p4[idx];
        mx = fmaxf(mx, g_pmx[idx]); mn = fminf(mn, g_pmn[idx]);
    }
    float n  = (float)SS;
    float mu = s1 / n;
    float e2 = s2 / n;
    float e3 = s3 / n;
    float e4 = s4 / n;
    float varu = (s2 - n * mu * mu) / (n - 1.f);
    if (varu < 0.f) varu = 0.f;
    float sd  = sqrtf(varu);
    float m3  = e3 - 3.f * mu * e2 + 2.f * mu * mu * mu;
    float m4  = e4 - 4.f * mu * e3 + 6.f * mu * mu * e2 - 3.f * mu * mu * mu * mu;
    float skew = m3 / (sd * sd * sd + 1e-8f);
    float kurt = m4 / (varu * varu + 1e-8f) - 3.f;
    float* f = g_feats + (size_t)b * K1;
    f[0 * HH + h] = mu;
    f[1 * HH + h] = sd;
    f[3 * HH + h] = mx;
    f[4 * HH + h] = mn;
    f[5 * HH + h] = skew;
    f[6 * HH + h] = kurt;
}

// ---------------- layer-1 GEMM: Kchunk=64, float4 over full N, + idcheck tail ----------------
__global__ __launch_bounds__(256) void k_gemm1(const float* __restrict__ W,
        const float* __restrict__ X, float* __restrict__ partial,
        const float* __restrict__ base) {
    __shared__ float xs[BB][64];
    int tid = threadIdx.x;
    int k0 = blockIdx.x * 64;
    xs[tid >> 6][tid & 63] = X[(size_t)(tid >> 6) * K1 + k0 + (tid & 63)];
    __syncthreads();
    int n4 = tid * 4;
    float4 acc[BB];
#pragma unroll
    for (int bq = 0; bq < BB; bq++) acc[bq] = make_float4(0.f, 0.f, 0.f, 0.f);
    const float* Wp = W + (size_t)k0 * N1 + n4;
#pragma unroll 8
    for (int kk = 0; kk < 64; kk++) {
        float4 w = *reinterpret_cast<const float4*>(Wp + (size_t)kk * N1);
#pragma unroll
        for (int bq = 0; bq < BB; bq++) {
            float h = xs[bq][kk];
            acc[bq].x += h * w.x; acc[bq].y += h * w.y;
            acc[bq].z += h * w.z; acc[bq].w += h * w.w;
        }
    }
    int p = blockIdx.x * BB;
#pragma unroll
    for (int bq = 0; bq < BB; bq++)
        *reinterpret_cast<float4*>(partial + (size_t)(p + bq) * N1 + n4) = acc[bq];

    // identity check of base_transform (flag was reset by k_moments, stream-ordered)
    int gtid = blockIdx.x * 256 + tid;
    bool bad = false;
    for (int i4 = gtid; i4 < HH * HH / 4; i4 += KSPLIT1 * 256) {
        int e0 = i4 * 4;
        int r = e0 >> 11, c0 = e0 & 2047;
        float4 x = *reinterpret_cast<const float4*>(base + e0);
        float4 e;
        e.x = (r == c0 + 0) ? 1.f : 0.f;
        e.y = (r == c0 + 1) ? 1.f : 0.f;
        e.z = (r == c0 + 2) ? 1.f : 0.f;
        e.w = (r == c0 + 3) ? 1.f : 0.f;
        if (x.x != e.x || x.y != e.y || x.z != e.z || x.w != e.w) bad = true;
    }
    if (bad) g_flag = 0;
}

// ---------------- small-M GEMM (M=4) with split-K (layers 2,3) ----------------
__global__ void k_gemm_sk(const float* __restrict__ W, const float* __restrict__ X,
                          float* __restrict__ partial, int K, int N, int Kchunk) {
    __shared__ float xs[BB][128];
    int n  = blockIdx.x * 256 + threadIdx.x;
    int k0 = blockIdx.y * Kchunk;
    for (int b = 0; b < BB; b++)
        for (int i = threadIdx.x; i < Kchunk; i += 256)
            xs[b][i] = X[(size_t)b * K + k0 + i];
    __syncthreads();
    if (n >= N) return;
    float a0 = 0.f, a1 = 0.f, a2 = 0.f, a3 = 0.f;
    const float* Wp = W + (size_t)k0 * N + n;
#pragma unroll 8
    for (int kk = 0; kk < Kchunk; kk++) {
        float w = Wp[(size_t)kk * N];
        a0 += xs[0][kk] * w; a1 += xs[1][kk] * w;
        a2 += xs[2][kk] * w; a3 += xs[3][kk] * w;
    }
    int p = blockIdx.y * BB;
    partial[(size_t)(p + 0) * N + n] = a0;
    partial[(size_t)(p + 1) * N + n] = a1;
    partial[(size_t)(p + 2) * N + n] = a2;
    partial[(size_t)(p + 3) * N + n] = a3;
}

__global__ void k_reduce_bias(const float* __restrict__ partial, const float* __restrict__ bias,
                              float* __restrict__ out, int N, int ksplit, int do_relu) {
    int i = blockIdx.x * 256 + threadIdx.x;
    if (i >= BB * N) return;
    int b = i / N, n = i % N;
    float a = bias[n];
#pragma unroll 8
    for (int ks = 0; ks < ksplit; ks++)
        a += partial[(size_t)(ks * BB + b) * N + n];
    if (do_relu) a = fmaxf(a, 0.f);
    out[i] = a;
}

// LayerNorm (population var, eps=1e-5) + ReLU
__global__ void k_ln_relu(const float* __restrict__ z, const float* __restrict__ g,
                          const float* __restrict__ beta, float* __restrict__ out, int N) {
    int b = blockIdx.x;
    const float* zr = z + (size_t)b * N;
    float s = 0.f, s2 = 0.f;
    for (int i = threadIdx.x; i < N; i += 256) { float x = zr[i]; s += x; s2 += x * x; }
    __shared__ float sha[256];
    __shared__ float shb[256];
    __shared__ float s_mean, s_rstd;
    sha[threadIdx.x] = s; shb[threadIdx.x] = s2; __syncthreads();
    for (int o = 128; o > 0; o >>= 1) {
        if (threadIdx.x < o) { sha[threadIdx.x] += sha[threadIdx.x + o]; shb[threadIdx.x] += shb[threadIdx.x + o]; }
        __syncthreads();
    }
    if (threadIdx.x == 0) {
        float mean = sha[0] / (float)N;
        float var  = shb[0] / (float)N - mean * mean;
        s_mean = mean;
        s_rstd = rsqrtf(var + 1e-5f);
    }
    __syncthreads();
    float mean = s_mean, rstd = s_rstd;
    for (int i = threadIdx.x; i < N; i += 256)
        out[(size_t)b * N + i] = fmaxf((zr[i] - mean) * rstd * g[i] + beta[i], 0.f);
}

// U/V heads. h3 is recomputed in-block from layer-3 split-K partials (+bias,ReLU):
// removes one serial launch; 4 KB redundant L2 reads per block.
__global__ __launch_bounds__(256) void k_uv(const float* __restrict__ Wu,
        const float* __restrict__ bu, const float* __restrict__ Wv,
        const float* __restrict__ bv, const float* __restrict__ su,
        const float* __restrict__ sv, const float* __restrict__ b3,
        const float* __restrict__ part3) {
    const int NU = HH * RR;
    int isv = blockIdx.y;
    const float* W    = isv ? Wv : Wu;
    const float* bias = isv ? bv : bu;
    float scale       = isv ? sv[0] : su[0];
    float* outp       = isv ? g_V : g_U;
    __shared__ float hsh[BB][N3];
    for (int i = threadIdx.x; i < BB * N3; i += 256) {
        int bq = i >> 8, nn = i & 255;
        float a = b3[nn];
#pragma unroll
        for (int ks = 0; ks < 4; ks++)
            a += part3[(size_t)(ks * BB + bq) * N3 + nn];
        hsh[bq][nn] = fmaxf(a, 0.f);
    }
    __syncthreads();
    int n = (blockIdx.x * 256 + threadIdx.x) * 4;
    float4 acc[BB];
#pragma unroll
    for (int bq = 0; bq < BB; bq++) acc[bq] = make_float4(0.f, 0.f, 0.f, 0.f);
    const float* Wp = W + n;
#pragma unroll 8
    for (int k = 0; k < N3; k++) {
        float4 w = *reinterpret_cast<const float4*>(Wp + (size_t)k * NU);
#pragma unroll
        for (int bq = 0; bq < BB; bq++) {
            float h = hsh[bq][k];
            acc[bq].x += h * w.x; acc[bq].y += h * w.y;
            acc[bq].z += h * w.z; acc[bq].w += h * w.w;
        }
    }
    float4 bb4 = *reinterpret_cast<const float4*>(bias + n);
#pragma unroll
    for (int bq = 0; bq < BB; bq++) {
        float4 o;
        o.x = tf32r((acc[bq].x + bb4.x) * scale);
        o.y = tf32r((acc[bq].y + bb4.y) * scale);
        o.z = tf32r((acc[bq].z + bb4.z) * scale);
        o.w = tf32r((acc[bq].w + bb4.w) * scale);
        *reinterpret_cast<float4*>(outp + (size_t)bq * NU + n) = o;
    }
}

// ---------------- T[b,s,r] = sum_h hs[b,s,h]*U[b,h,r]  (tf32 tensor cores) ----------------
__global__ __launch_bounds__(256) void k_T(const float* __restrict__ hs) {
    __shared__ float As[64][36];
    __shared__ float Us[32][72];
    int b   = blockIdx.y;
    int s0  = blockIdx.x * 64;
    int tid = threadIdx.x;
    int warp = tid >> 5, lane = tid & 31;
    int gid = lane >> 2, tig = lane & 3;
    int wm = warp & 3, wn = warp >> 2;
    const float* A = hs  + ((size_t)b * SS + s0) * HH;
    const float* U = g_U + (size_t)b * HH * RR;

    int laR[2], laC[2], luR[2], luC[2];
#pragma unroll
    for (int j = 0; j < 2; j++) {
        int lin = tid + j * 256;
        laR[j] = lin >> 3;  laC[j] = (lin & 7)  << 2;   // A: 64 x 32
        luR[j] = lin >> 4;  luC[j] = (lin & 15) << 2;   // U: 32 x 64
    }
    float4 fa[2], fu[2];
#pragma unroll
    for (int j = 0; j < 2; j++) {
        fa[j] = *reinterpret_cast<const float4*>(A + (size_t)laR[j] * HH + laC[j]);
        fu[j] = *reinterpret_cast<const float4*>(U + (size_t)luR[j] * RR + luC[j]);
    }

    float acc[4][4] = {};
    for (int h0 = 0; h0 < HH; h0 += 32) {
        if (h0) __syncthreads();
#pragma unroll
        for (int j = 0; j < 2; j++) {
            float* pA = &As[laR[j]][laC[j]];
            pA[0] = tf32r(fa[j].x); pA[1] = tf32r(fa[j].y);
            pA[2] = tf32r(fa[j].z); pA[3] = tf32r(fa[j].w);
            *reinterpret_cast<float2*>(&Us[luR[j]][luC[j]])     = make_float2(fu[j].x, fu[j].y);
            *reinterpret_cast<float2*>(&Us[luR[j]][luC[j] + 2]) = make_float2(fu[j].z, fu[j].w);
        }
        __syncthreads();
        if (h0 + 32 < HH) {
#pragma unroll
            for (int j = 0; j < 2; j++) {
                fa[j] = *reinterpret_cast<const float4*>(A + (size_t)laR[j] * HH + h0 + 32 + laC[j]);
                fu[j] = *reinterpret_cast<const float4*>(U + (size_t)(h0 + 32 + luR[j]) * RR + luC[j]);
            }
        }
#pragma unroll
        for (int ks = 0; ks < 4; ks++) {
            int kk = ks * 8;
            uint32_t a0 = __float_as_uint(As[wm * 16 + gid    ][kk + tig]);
            uint32_t a1 = __float_as_uint(As[wm * 16 + gid + 8][kk + tig]);
            uint32_t a2 = __float_as_uint(As[wm * 16 + gid    ][kk + tig + 4]);
            uint32_t a3 = __float_as_uint(As[wm * 16 + gid + 8][kk + tig + 4]);
#pragma unroll
            for (int nt = 0; nt < 4; nt++) {
                int nc = wn * 32 + nt * 8 + gid;
                uint32_t b0 = __float_as_uint(Us[kk + tig    ][nc]);
                uint32_t b1 = __float_as_uint(Us[kk + tig + 4][nc]);
                mma_tf32(acc[nt], a0, a1, a2, a3, b0, b1);
            }
        }
    }
    float* T = g_T + ((size_t)b * SS + s0 + wm * 16) * RR + wn * 32;
#pragma unroll
    for (int nt = 0; nt < 4; nt++) {
        int c = nt * 8 + 2 * tig;
        *reinterpret_cast<float2*>(T + (size_t)(gid    ) * RR + c) =
            make_float2(tf32r(acc[nt][0]), tf32r(acc[nt][1]));
        *reinterpret_cast<float2*>(T + (size_t)(gid + 8) * RR + c) =
            make_float2(tf32r(acc[nt][2]), tf32r(acc[nt][3]));
    }
}

// fallback: g_hsb = hs @ base (only when base != I; early-exits otherwise). 8 k-tiles/block.
__global__ void k_basegemm(const float* __restrict__ hs, const float* __restrict__ base) {
    if (g_flag) return;
    __shared__ float As2[64][17];
    __shared__ float Bs2[16][64];
    int b   = blockIdx.z;
    int s0  = blockIdx.y * 64;
    int tid = threadIdx.x, tx = tid % 16, ty = tid / 16;
    const float* A = hs + ((size_t)b * SS + s0) * HH;
    for (int kt = 0; kt < 8; kt++) {
        int k0t = (blockIdx.x * 8 + kt) * 64;
        float acc[4][4] = {};
        for (int h0 = 0; h0 < HH; h0 += 16) {
#pragma unroll
            for (int j = 0; j < 4; j++) {
                int idx = tid + j * 256, r = idx / 16, c = idx % 16;
                As2[r][c] = A[(size_t)r * HH + h0 + c];
            }
#pragma unroll
            for (int j = 0; j < 4; j++) {
                int idx = tid + j * 256, r = idx / 64, c = idx % 64;
                Bs2[r][c] = base[(size_t)(h0 + r) * HH + k0t + c];
            }
            __syncthreads();
#pragma unroll
            for (int kk = 0; kk < 16; kk++) {
                float af[4], bf[4];
#pragma unroll
                for (int i = 0; i < 4; i++) af[i] = As2[ty * 4 + i][kk];
#pragma unroll
                for (int j = 0; j < 4; j++) bf[j] = Bs2[kk][tx * 4 + j];
#pragma unroll
                for (int i = 0; i < 4; i++)
#pragma unroll
                    for (int j = 0; j < 4; j++) acc[i][j] += af[i] * bf[j];
            }
            __syncthreads();
        }
        float* Op = g_hsb + ((size_t)b * SS + s0) * HH + k0t;
#pragma unroll
        for (int i = 0; i < 4; i++) {
            float4 v = make_float4(acc[i][0], acc[i][1], acc[i][2], acc[i][3]);
            *reinterpret_cast<float4*>(Op + (size_t)(ty * 4 + i) * HH + tx * 4) = v;
        }
    }
}

// ---------------- out = rw*src + (1-rw)*T@V  (tf32, 2 k-tiles/block, V prefetch) ----------------
__global__ __launch_bounds__(128) void k_final(const float* __restrict__ hs,
                                               const float* __restrict__ rw_p,
                                               float* __restrict__ out) {
    __shared__ float Ts[64][68];
    __shared__ float Vs[64][72];
    int b  = blockIdx.z;
    int s0 = blockIdx.y * 64;
    int k0 = blockIdx.x * 128;
    int tid = threadIdx.x;
    int warp = tid >> 5, lane = tid & 31;
    int gid = lane >> 2, tig = lane & 3;
    float rw = rw_p[0];
    float cw = 1.f - rw;
    const float* src = g_flag ? hs : (const float*)g_hsb;
    const float* Tg = g_T + ((size_t)b * SS + s0) * RR;
    const float* Vg = g_V + (size_t)b * RR * HH + k0;

#pragma unroll
    for (int j = 0; j < 8; j++) {
        int lin = tid + j * 128;
        int r = lin >> 4, c = (lin & 15) << 2;
        float4 t = *reinterpret_cast<const float4*>(Tg + (size_t)r * RR + c);
        *reinterpret_cast<float2*>(&Ts[r][c])     = make_float2(t.x, t.y);
        *reinterpret_cast<float2*>(&Ts[r][c + 2]) = make_float2(t.z, t.w);
        *reinterpret_cast<float4*>(&Vs[r][c]) =
            *reinterpret_cast<const float4*>(Vg + (size_t)r * HH + c);
    }
    __syncthreads();

    float4 afr[8];
#pragma unroll
    for (int ks = 0; ks < 8; ks++) {
        int kk = ks * 8;
        afr[ks].x = Ts[warp * 16 + gid    ][kk + tig];
        afr[ks].y = Ts[warp * 16 + gid + 8][kk + tig];
        afr[ks].z = Ts[warp * 16 + gid    ][kk + tig + 4];
        afr[ks].w = Ts[warp * 16 + gid + 8][kk + tig + 4];
    }

    // prefetch V tile 1 into registers while computing tile 0
    float4 vpf[8];
#pragma unroll
    for (int j = 0; j < 8; j++) {
        int lin = tid + j * 128;
        int r = lin >> 4, c = (lin & 15) << 2;
        vpf[j] = *reinterpret_cast<const float4*>(Vg + 64 + (size_t)r * HH + c);
    }

#pragma unroll 1
    for (int tile = 0; tile < 2; tile++) {
        if (tile) {
            __syncthreads();   // all warps done reading Vs(tile 0)
#pragma unroll
            for (int j = 0; j < 8; j++) {
                int lin = tid + j * 128;
                int r = lin >> 4, c = (lin & 15) << 2;
                *reinterpret_cast<float4*>(&Vs[r][c]) = vpf[j];
            }
            __syncthreads();
        }
        float acc[8][4] = {};
#pragma unroll
        for (int ks = 0; ks < 8; ks++) {
            int kk = ks * 8;
            uint32_t a0 = __float_as_uint(afr[ks].x);
            uint32_t a1 = __float_as_uint(afr[ks].y);
            uint32_t a2 = __float_as_uint(afr[ks].z);
            uint32_t a3 = __float_as_uint(afr[ks].w);
#pragma unroll
            for (int nt = 0; nt < 8; nt++) {
                uint32_t b0 = __float_as_uint(Vs[kk + tig    ][nt * 8 + gid]);
                uint32_t b1 = __float_as_uint(Vs[kk + tig + 4][nt * 8 + gid]);
                mma_tf32(acc[nt], a0, a1, a2, a3, b0, b1);
            }
        }
        size_t rowA = ((size_t)b * SS + s0 + warp * 16 + gid    ) * HH + k0 + tile * 64;
        size_t rowB = rowA + (size_t)8 * HH;
#pragma unroll
        for (int nt = 0; nt < 8; nt++) {
            int c = nt * 8 + 2 * tig;
            float2 xa = *reinterpret_cast<const float2*>(src + rowA + c);
            float2 xb = *reinterpret_cast<const float2*>(src + rowB + c);
            float2 oa = make_float2(rw * xa.x + cw * acc[nt][0], rw * xa.y + cw * acc[nt][1]);
            float2 ob = make_float2(rw * xb.x + cw * acc[nt][2], rw * xb.y + cw * acc[nt][3]);
            *reinterpret_cast<float2*>(out + rowA + c) = oa;
            *reinterpret_cast<float2*>(out + rowB + c) = ob;
        }
    }
}

// ---------------- launch ----------------
extern "C" void kernel_launch(void* const* d_in, const int* in_sizes, int n_in,
                              void* d_out, int out_size) {
    const float* hs  = (const float*)d_in[0];
    const float* W1  = (const float*)d_in[1];
    const float* b1  = (const float*)d_in[2];
    const float* g1  = (const float*)d_in[3];
    const float* be1 = (const float*)d_in[4];
    const float* W2  = (const float*)d_in[5];
    const float* b2  = (const float*)d_in[6];
    const float* g2  = (const float*)d_in[7];
    const float* be2 = (const float*)d_in[8];
    const float* W3  = (const float*)d_in[9];
    const float* b3  = (const float*)d_in[10];
    const float* Wu  = (const float*)d_in[11];
    const float* bu  = (const float*)d_in[12];
    const float* Wv  = (const float*)d_in[13];
    const float* bv  = (const float*)d_in[14];
    const float* su  = (const float*)d_in[15];
    const float* sv  = (const float*)d_in[16];
    const float* rw  = (const float*)d_in[17];
    const float* base= (const float*)d_in[18];
    float* out = (float*)d_out;

    float *p_feats, *p_part, *p_z1, *p_z2, *p_h1, *p_h2;
    cudaGetSymbolAddress((void**)&p_feats, g_feats);
    cudaGetSymbolAddress((void**)&p_part,  g_partial);
    cudaGetSymbolAddress((void**)&p_z1,    g_z1);
    cudaGetSymbolAddress((void**)&p_z2,    g_z2);
    cudaGetSymbolAddress((void**)&p_h1,    g_h1);
    cudaGetSymbolAddress((void**)&p_h2,    g_h2);

    k_moments<<<dim3(HH / 256, BB, NSPLIT), 256>>>(hs);
    k_combine_nrm<<<dim3(9, BB), 256>>>();

    // layer 1: [4,14336] @ [14336,1024], Kchunk=64 -> 224 blocks (+ idcheck tail)
    k_gemm1<<<KSPLIT1, 256>>>(W1, p_feats, p_part, base);
    k_reduce_bias<<<(BB * N1 + 255) / 256, 256>>>(p_part, b1, p_z1, N1, KSPLIT1, 0);
    k_ln_relu<<<BB, 256>>>(p_z1, g1, be1, p_h1, N1);
    // layer 2: [4,1024] @ [1024,512]
    k_gemm_sk<<<dim3(N2 / 256, 8), 256>>>(W2, p_h1, p_part, N1, N2, 128);
    k_reduce_bias<<<(BB * N2 + 255) / 256, 256>>>(p_part, b2, p_z2, N2, 8, 0);
    k_ln_relu<<<BB, 256>>>(p_z2, g2, be2, p_h2, N2);
    // layer 3: [4,512] @ [512,256] -> partials consumed by k_uv
    k_gemm_sk<<<dim3(1, 4), 256>>>(W3, p_h2, p_part, N2, N3, 128);

    k_uv<<<dim3(HH * RR / 1024, 2), 256>>>(Wu, bu, Wv, bv, su, sv, b3, p_part);
    k_T<<<dim3(SS / 64, BB), 256>>>(hs);
    k_basegemm<<<dim3(HH / 512, SS / 64, BB), 256>>>(hs, base);
    k_final<<<dim3(HH / 128, SS / 64, BB), 128>>>(hs, rw, out);
}

// round 15
// speedup vs baseline: 1.1153x; 1.0192x over previous
#include <cuda_runtime.h>
#include <math.h>
#include <stdint.h>

#define BB 4
#define SS 4096
#define HH 2048
#define RR 64
#define K1 (HH * 7)      // 14336
#define N1 1024
#define N2 512
#define N3 256
#define NSPLIT 32
#define SCHUNK (SS / NSPLIT)   // 128 s rows per block
#define SUB 32                 // s rows per smem sub-tile
#define KSPLIT1 224            // layer-1 split-K chunks (Kchunk=64)
#define KRED 8                 // second-stage reduction width

// ---------------- scratch (__device__ globals; no allocations) ----------------
__device__ float g_p1[NSPLIT * BB * HH];
__device__ float g_p2[NSPLIT * BB * HH];
__device__ float g_p3[NSPLIT * BB * HH];
__device__ float g_p4[NSPLIT * BB * HH];
__device__ float g_pmx[NSPLIT * BB * HH];
__device__ float g_pmn[NSPLIT * BB * HH];
__device__ float g_rn2[8 * BB * SS];   // rownorm sum-of-squares partials (8 h-slices)
__device__ float g_feats[BB * K1];
__device__ float g_partial[KSPLIT1 * BB * N1];
__device__ float g_part2[KRED * BB * N1];
__device__ float g_h1[BB * N1];
__device__ float g_h2[BB * N2];
__device__ float g_U[BB * HH * RR];   // [b][h][r]  (tf32-rounded)
__device__ float g_V[BB * RR * HH];   // [b][r][h]  (tf32-rounded)
__device__ float g_T[BB * SS * RR];   // hs @ U     (tf32-rounded)
__device__ float g_hsb[(size_t)BB * SS * HH];  // hs @ base (general fallback only)
__device__ int   g_flag;              // 1 = base_transform is identity

// ---------------- tf32 mma helpers ----------------
__device__ __forceinline__ float tf32r(float x) {
    uint32_t u;
    asm("cvt.rna.tf32.f32 %0, %1;" : "=r"(u) : "f"(x));
    return __uint_as_float(u);
}
__device__ __forceinline__ void mma_tf32(float* c,
        uint32_t a0, uint32_t a1, uint32_t a2, uint32_t a3,
        uint32_t b0, uint32_t b1) {
    asm volatile(
        "mma.sync.aligned.m16n8k8.row.col.f32.tf32.tf32.f32 "
        "{%0,%1,%2,%3}, {%4,%5,%6,%7}, {%8,%9}, {%0,%1,%2,%3};"
        : "+f"(c[0]), "+f"(c[1]), "+f"(c[2]), "+f"(c[3])
        : "r"(a0), "r"(a1), "r"(a2), "r"(a3), "r"(b0), "r"(b1));
}

// ---------------- moments + rownorm, fused via smem tiles ----------------
__global__ __launch_bounds__(256) void k_moments(const float* __restrict__ hs) {
    __shared__ float tile[SUB][260];
    int h0 = blockIdx.x * 256;
    int b  = blockIdx.y;
    int sp = blockIdx.z;
    int tid = threadIdx.x;
    int warp = tid >> 5, lane = tid & 31;
    const float* base = hs + ((size_t)b * SS + (size_t)sp * SCHUNK) * HH + h0;

    float s1 = 0.f, s2 = 0.f, s3 = 0.f, s4 = 0.f;
    float mx = -1e30f, mn = 1e30f;

    float4 pf[8];
#pragma unroll
    for (int j = 0; j < 8; j++) {
        int lin = tid + j * 256;
        int r = lin >> 6, c = (lin & 63) << 2;
        pf[j] = *reinterpret_cast<const float4*>(base + (size_t)r * HH + c);
    }

#pragma unroll 1
    for (int st = 0; st < 4; st++) {
        if (st) __syncthreads();
#pragma unroll
        for (int j = 0; j < 8; j++) {
            int lin = tid + j * 256;
            int r = lin >> 6, c = (lin & 63) << 2;
            *reinterpret_cast<float4*>(&tile[r][c]) = pf[j];
        }
        __syncthreads();
        if (st < 3) {
#pragma unroll
            for (int j = 0; j < 8; j++) {
                int lin = tid + j * 256;
                int r = lin >> 6, c = (lin & 63) << 2;
                pf[j] = *reinterpret_cast<const float4*>(
                    base + (size_t)((st + 1) * SUB + r) * HH + c);
            }
        }
#pragma unroll
        for (int s = 0; s < SUB; s++) {
            float x  = tile[s][tid];
            float x2 = x * x;
            s1 += x; s2 += x2; s3 += x2 * x; s4 += x2 * x2;
            mx = fmaxf(mx, x); mn = fminf(mn, x);
        }
#pragma unroll
        for (int i = 0; i < 4; i++) {
            int r = warp * 4 + i;
            float4 a  = *reinterpret_cast<const float4*>(&tile[r][lane * 4]);
            float4 bq = *reinterpret_cast<const float4*>(&tile[r][lane * 4 + 128]);
            float v = (a.x * a.x + a.y * a.y) + (a.z * a.z + a.w * a.w)
                    + (bq.x * bq.x + bq.y * bq.y) + (bq.z * bq.z + bq.w * bq.w);
#pragma unroll
            for (int o = 16; o > 0; o >>= 1) v += __shfl_xor_sync(0xffffffffu, v, o);
            if (lane == 0)
                g_rn2[blockIdx.x * (BB * SS) + b * SS + sp * SCHUNK + st * SUB + r] = v;
        }
    }
    int idx = (sp * BB + b) * HH + h0 + tid;
    g_p1[idx] = s1; g_p2[idx] = s2; g_p3[idx] = s3; g_p4[idx] = s4;
    g_pmx[idx] = mx; g_pmn[idx] = mn;
    if (blockIdx.x == 0 && blockIdx.y == 0 && blockIdx.z == 0 && tid == 0)
        g_flag = 1;   // reset identity flag; checked by k_gemm1 (later in stream)
}

// combine chunk partials -> features; blockIdx.x==8 lane does the rownorm mean
__global__ void k_combine_nrm() {
    int b = blockIdx.y;
    if (blockIdx.x == 8) {
        float acc = 0.f;
        for (int i = threadIdx.x; i < SS; i += 256) {
            float v = 0.f;
#pragma unroll
            for (int hsl = 0; hsl < 8; hsl++) v += g_rn2[hsl * (BB * SS) + b * SS + i];
            acc += sqrtf(v);
        }
        __shared__ float sh[256];
        __shared__ float nrm;
        sh[threadIdx.x] = acc; __syncthreads();
        for (int o = 128; o > 0; o >>= 1) {
            if (threadIdx.x < o) sh[threadIdx.x] += sh[threadIdx.x + o];
            __syncthreads();
        }
        if (threadIdx.x == 0) nrm = sh[0] / (float)SS;
        __syncthreads();
        for (int h = threadIdx.x; h < HH; h += 256)
            g_feats[(size_t)b * K1 + 2 * HH + h] = nrm;
        return;
    }
    int h = blockIdx.x * 256 + threadIdx.x;
    float s1 = 0.f, s2 = 0.f, s3 = 0.f, s4 = 0.f;
    float mx = -1e30f, mn = 1e30f;
#pragma unroll
    for (int sp = 0; sp < NSPLIT; sp++) {
        int idx = (sp * BB + b) * HH + h;
        s1 += g_p1[idx]; s2 += g_p2[idx]; s3 += g_p3[idx]; s4 += g_p4[idx];
        mx = fmaxf(mx, g_pmx[idx]); mn = fminf(mn, g_pmn[idx]);
    }
    float n  = (float)SS;
    float mu = s1 / n;
    float e2 = s2 / n;
    float e3 = s3 / n;
    float e4 = s4 / n;
    float varu = (s2 - n * mu * mu) / (n - 1.f);
    if (varu < 0.f) varu = 0.f;
    float sd  = sqrtf(varu);
    float m3  = e3 - 3.f * mu * e2 + 2.f * mu * mu * mu;
    float m4  = e4 - 4.f * mu * e3 + 6.f * mu * mu * e2 - 3.f * mu * mu * mu * mu;
    float skew = m3 / (sd * sd * sd + 1e-8f);
    float kurt = m4 / (varu * varu + 1e-8f) - 3.f;
    float* f = g_feats + (size_t)b * K1;
    f[0 * HH + h] = mu;
    f[1 * HH + h] = sd;
    f[3 * HH + h] = mx;
    f[4 * HH + h] = mn;
    f[5 * HH + h] = skew;
    f[6 * HH + h] = kurt;
}

// ---------------- layer-1 GEMM: Kchunk=64, float4 over full N, + idcheck tail ----------------
__global__ __launch_bounds__(256) void k_gemm1(const float* __restrict__ W,
        const float* __restrict__ X, float* __restrict__ partial,
        const float* __restrict__ base) {
    __shared__ float xs[BB][64];
    int tid = threadIdx.x;
    int k0 = blockIdx.x * 64;
    xs[tid >> 6][tid & 63] = X[(size_t)(tid >> 6) * K1 + k0 + (tid & 63)];
    __syncthreads();
    int n4 = tid * 4;
    float4 acc[BB];
#pragma unroll
    for (int bq = 0; bq < BB; bq++) acc[bq] = make_float4(0.f, 0.f, 0.f, 0.f);
    const float* Wp = W + (size_t)k0 * N1 + n4;
#pragma unroll 8
    for (int kk = 0; kk < 64; kk++) {
        float4 w = *reinterpret_cast<const float4*>(Wp + (size_t)kk * N1);
#pragma unroll
        for (int bq = 0; bq < BB; bq++) {
            float h = xs[bq][kk];
            acc[bq].x += h * w.x; acc[bq].y += h * w.y;
            acc[bq].z += h * w.z; acc[bq].w += h * w.w;
        }
    }
    int p = blockIdx.x * BB;
#pragma unroll
    for (int bq = 0; bq < BB; bq++)
        *reinterpret_cast<float4*>(partial + (size_t)(p + bq) * N1 + n4) = acc[bq];

    // identity check of base_transform (flag was reset by k_moments, stream-ordered)
    int gtid = blockIdx.x * 256 + tid;
    bool bad = false;
    for (int i4 = gtid; i4 < HH * HH / 4; i4 += KSPLIT1 * 256) {
        int e0 = i4 * 4;
        int r = e0 >> 11, c0 = e0 & 2047;
        float4 x = *reinterpret_cast<const float4*>(base + e0);
        float4 e;
        e.x = (r == c0 + 0) ? 1.f : 0.f;
        e.y = (r == c0 + 1) ? 1.f : 0.f;
        e.z = (r == c0 + 2) ? 1.f : 0.f;
        e.w = (r == c0 + 3) ? 1.f : 0.f;
        if (x.x != e.x || x.y != e.y || x.z != e.z || x.w != e.w) bad = true;
    }
    if (bad) g_flag = 0;
}

// ---------------- stage-1 reduce: 224 partials -> 8, parallel over ks groups ----------------
// grid (BB*N1/256, KRED); thread sums 28 coalesced L2-resident rows.
__global__ __launch_bounds__(256) void k_reduce1(const float* __restrict__ partial,
        float* __restrict__ part2) {
    int i   = blockIdx.x * 256 + threadIdx.x;   // flat (b,n)
    int ksg = blockIdx.y;
    const int GRP = KSPLIT1 / KRED;             // 28
    float a = 0.f;
    const float* p = partial + (size_t)(ksg * GRP * BB) * N1 + i;
#pragma unroll 7
    for (int ks = 0; ks < GRP; ks++)
        a += p[(size_t)ks * BB * N1];
    part2[(size_t)ksg * BB * N1 + i] = a;
}

// ---------------- fused ksplit-reduce + bias + LayerNorm + ReLU ----------------
// one block per batch; N/256 elements per thread (strided, coalesced); ksplit<=8.
__global__ __launch_bounds__(256) void k_lnr(const float* __restrict__ partial,
        const float* __restrict__ bias, const float* __restrict__ g,
        const float* __restrict__ beta, float* __restrict__ out, int N, int ksplit) {
    int b = blockIdx.x, t = threadIdx.x;
    int nper = N >> 8;   // 4 (N1) or 2 (N2)
    float a[4];
    float s = 0.f, s2 = 0.f;
    for (int j = 0; j < nper; j++) {
        int n = t + j * 256;
        float v = bias[n];
        for (int ks = 0; ks < ksplit; ks++)
            v += partial[(size_t)(ks * BB + b) * N + n];
        a[j] = v;
        s += v; s2 += v * v;
    }
    __shared__ float sha[256];
    __shared__ float shb[256];
    __shared__ float s_mean, s_rstd;
    sha[t] = s; shb[t] = s2; __syncthreads();
    for (int o = 128; o > 0; o >>= 1) {
        if (t < o) { sha[t] += sha[t + o]; shb[t] += shb[t + o]; }
        __syncthreads();
    }
    if (t == 0) {
        float mean = sha[0] / (float)N;
        float var  = shb[0] / (float)N - mean * mean;
        s_mean = mean;
        s_rstd = rsqrtf(var + 1e-5f);
    }
    __syncthreads();
    float mean = s_mean, rstd = s_rstd;
    for (int j = 0; j < nper; j++) {
        int n = t + j * 256;
        out[(size_t)b * N + n] = fmaxf((a[j] - mean) * rstd * g[n] + beta[n], 0.f);
    }
}

// ---------------- small-M GEMM (M=4) with split-K (layers 2,3) ----------------
__global__ void k_gemm_sk(const float* __restrict__ W, const float* __restrict__ X,
                          float* __restrict__ partial, int K, int N, int Kchunk) {
    __shared__ float xs[BB][128];
    int n  = blockIdx.x * 256 + threadIdx.x;
    int k0 = blockIdx.y * Kchunk;
    for (int b = 0; b < BB; b++)
        for (int i = threadIdx.x; i < Kchunk; i += 256)
            xs[b][i] = X[(size_t)b * K + k0 + i];
    __syncthreads();
    if (n >= N) return;
    float a0 = 0.f, a1 = 0.f, a2 = 0.f, a3 = 0.f;
    const float* Wp = W + (size_t)k0 * N + n;
#pragma unroll 8
    for (int kk = 0; kk < Kchunk; kk++) {
        float w = Wp[(size_t)kk * N];
        a0 += xs[0][kk] * w; a1 += xs[1][kk] * w;
        a2 += xs[2][kk] * w; a3 += xs[3][kk] * w;
    }
    int p = blockIdx.y * BB;
    partial[(size_t)(p + 0) * N + n] = a0;
    partial[(size_t)(p + 1) * N + n] = a1;
    partial[(size_t)(p + 2) * N + n] = a2;
    partial[(size_t)(p + 3) * N + n] = a3;
}

// U/V heads. h3 recomputed in-block from layer-3 split-K partials (+bias,ReLU).
__global__ __launch_bounds__(256) void k_uv(const float* __restrict__ Wu,
        const float* __restrict__ bu, const float* __restrict__ Wv,
        const float* __restrict__ bv, const float* __restrict__ su,
        const float* __restrict__ sv, const float* __restrict__ b3,
        const float* __restrict__ part3) {
    const int NU = HH * RR;
    int isv = blockIdx.y;
    const float* W    = isv ? Wv : Wu;
    const float* bias = isv ? bv : bu;
    float scale       = isv ? sv[0] : su[0];
    float* outp       = isv ? g_V : g_U;
    __shared__ float hsh[BB][N3];
    for (int i = threadIdx.x; i < BB * N3; i += 256) {
        int bq = i >> 8, nn = i & 255;
        float a = b3[nn];
#pragma unroll
        for (int ks = 0; ks < 4; ks++)
            a += part3[(size_t)(ks * BB + bq) * N3 + nn];
        hsh[bq][nn] = fmaxf(a, 0.f);
    }
    __syncthreads();
    int n = (blockIdx.x * 256 + threadIdx.x) * 4;
    float4 acc[BB];
#pragma unroll
    for (int bq = 0; bq < BB; bq++) acc[bq] = make_float4(0.f, 0.f, 0.f, 0.f);
    const float* Wp = W + n;
#pragma unroll 8
    for (int k = 0; k < N3; k++) {
        float4 w = *reinterpret_cast<const float4*>(Wp + (size_t)k * NU);
#pragma unroll
        for (int bq = 0; bq < BB; bq++) {
            float h = hsh[bq][k];
            acc[bq].x += h * w.x; acc[bq].y += h * w.y;
            acc[bq].z += h * w.z; acc[bq].w += h * w.w;
        }
    }
    float4 bb4 = *reinterpret_cast<const float4*>(bias + n);
#pragma unroll
    for (int bq = 0; bq < BB; bq++) {
        float4 o;
        o.x = tf32r((acc[bq].x + bb4.x) * scale);
        o.y = tf32r((acc[bq].y + bb4.y) * scale);
        o.z = tf32r((acc[bq].z + bb4.z) * scale);
        o.w = tf32r((acc[bq].w + bb4.w) * scale);
        *reinterpret_cast<float4*>(outp + (size_t)bq * NU + n) = o;
    }
}

// ---------------- T[b,s,r] = sum_h hs[b,s,h]*U[b,h,r]  (tf32 tensor cores) ----------------
__global__ __launch_bounds__(256) void k_T(const float* __restrict__ hs) {
    __shared__ float As[64][36];
    __shared__ float Us[32][72];
    int b   = blockIdx.y;
    int s0  = blockIdx.x * 64;
    int tid = threadIdx.x;
    int warp = tid >> 5, lane = tid & 31;
    int gid = lane >> 2, tig = lane & 3;
    int wm = warp & 3, wn = warp >> 2;
    const float* A = hs  + ((size_t)b * SS + s0) * HH;
    const float* U = g_U + (size_t)b * HH * RR;

    int laR[2], laC[2], luR[2], luC[2];
#pragma unroll
    for (int j = 0; j < 2; j++) {
        int lin = tid + j * 256;
        laR[j] = lin >> 3;  laC[j] = (lin & 7)  << 2;   // A: 64 x 32
        luR[j] = lin >> 4;  luC[j] = (lin & 15) << 2;   // U: 32 x 64
    }
    float4 fa[2], fu[2];
#pragma unroll
    for (int j = 0; j < 2; j++) {
        fa[j] = *reinterpret_cast<const float4*>(A + (size_t)laR[j] * HH + laC[j]);
        fu[j] = *reinterpret_cast<const float4*>(U + (size_t)luR[j] * RR + luC[j]);
    }

    float acc[4][4] = {};
    for (int h0 = 0; h0 < HH; h0 += 32) {
        if (h0) __syncthreads();
#pragma unroll
        for (int j = 0; j < 2; j++) {
            float* pA = &As[laR[j]][laC[j]];
            pA[0] = tf32r(fa[j].x); pA[1] = tf32r(fa[j].y);
            pA[2] = tf32r(fa[j].z); pA[3] = tf32r(fa[j].w);
            *reinterpret_cast<float2*>(&Us[luR[j]][luC[j]])     = make_float2(fu[j].x, fu[j].y);
            *reinterpret_cast<float2*>(&Us[luR[j]][luC[j] + 2]) = make_float2(fu[j].z, fu[j].w);
        }
        __syncthreads();
        if (h0 + 32 < HH) {
#pragma unroll
            for (int j = 0; j < 2; j++) {
                fa[j] = *reinterpret_cast<const float4*>(A + (size_t)laR[j] * HH + h0 + 32 + laC[j]);
                fu[j] = *reinterpret_cast<const float4*>(U + (size_t)(h0 + 32 + luR[j]) * RR + luC[j]);
            }
        }
#pragma unroll
        for (int ks = 0; ks < 4; ks++) {
            int kk = ks * 8;
            uint32_t a0 = __float_as_uint(As[wm * 16 + gid    ][kk + tig]);
            uint32_t a1 = __float_as_uint(As[wm * 16 + gid + 8][kk + tig]);
            uint32_t a2 = __float_as_uint(As[wm * 16 + gid    ][kk + tig + 4]);
            uint32_t a3 = __float_as_uint(As[wm * 16 + gid + 8][kk + tig + 4]);
#pragma unroll
            for (int nt = 0; nt < 4; nt++) {
                int nc = wn * 32 + nt * 8 + gid;
                uint32_t b0 = __float_as_uint(Us[kk + tig    ][nc]);
                uint32_t b1 = __float_as_uint(Us[kk + tig + 4][nc]);
                mma_tf32(acc[nt], a0, a1, a2, a3, b0, b1);
            }
        }
    }
    float* T = g_T + ((size_t)b * SS + s0 + wm * 16) * RR + wn * 32;
#pragma unroll
    for (int nt = 0; nt < 4; nt++) {
        int c = nt * 8 + 2 * tig;
        *reinterpret_cast<float2*>(T + (size_t)(gid    ) * RR + c) =
            make_float2(tf32r(acc[nt][0]), tf32r(acc[nt][1]));
        *reinterpret_cast<float2*>(T + (size_t)(gid + 8) * RR + c) =
            make_float2(tf32r(acc[nt][2]), tf32r(acc[nt][3]));
    }
}

// fallback: g_hsb = hs @ base (only when base != I; early-exits otherwise). 8 k-tiles/block.
__global__ void k_basegemm(const float* __restrict__ hs, const float* __restrict__ base) {
    if (g_flag) return;
    __shared__ float As2[64][17];
    __shared__ float Bs2[16][64];
    int b   = blockIdx.z;
    int s0  = blockIdx.y * 64;
    int tid = threadIdx.x, tx = tid % 16, ty = tid / 16;
    const float* A = hs + ((size_t)b * SS + s0) * HH;
    for (int kt = 0; kt < 8; kt++) {
        int k0t = (blockIdx.x * 8 + kt) * 64;
        float acc[4][4] = {};
        for (int h0 = 0; h0 < HH; h0 += 16) {
#pragma unroll
            for (int j = 0; j < 4; j++) {
                int idx = tid + j * 256, r = idx / 16, c = idx % 16;
                As2[r][c] = A[(size_t)r * HH + h0 + c];
            }
#pragma unroll
            for (int j = 0; j < 4; j++) {
                int idx = tid + j * 256, r = idx / 64, c = idx % 64;
                Bs2[r][c] = base[(size_t)(h0 + r) * HH + k0t + c];
            }
            __syncthreads();
#pragma unroll
            for (int kk = 0; kk < 16; kk++) {
                float af[4], bf[4];
#pragma unroll
                for (int i = 0; i < 4; i++) af[i] = As2[ty * 4 + i][kk];
#pragma unroll
                for (int j = 0; j < 4; j++) bf[j] = Bs2[kk][tx * 4 + j];
#pragma unroll
                for (int i = 0; i < 4; i++)
#pragma unroll
                    for (int j = 0; j < 4; j++) acc[i][j] += af[i] * bf[j];
            }
            __syncthreads();
        }
        float* Op = g_hsb + ((size_t)b * SS + s0) * HH + k0t;
#pragma unroll
        for (int i = 0; i < 4; i++) {
            float4 v = make_float4(acc[i][0], acc[i][1], acc[i][2], acc[i][3]);
            *reinterpret_cast<float4*>(Op + (size_t)(ty * 4 + i) * HH + tx * 4) = v;
        }
    }
}

// ---------------- out = rw*src + (1-rw)*T@V  (tf32, 2 k-tiles/block, V prefetch) ----------------
__global__ __launch_bounds__(128) void k_final(const float* __restrict__ hs,
                                               const float* __restrict__ rw_p,
                                               float* __restrict__ out) {
    __shared__ float Ts[64][68];
    __shared__ float Vs[64][72];
    int b  = blockIdx.z;
    int s0 = blockIdx.y * 64;
    int k0 = blockIdx.x * 128;
    int tid = threadIdx.x;
    int warp = tid >> 5, lane = tid & 31;
    int gid = lane >> 2, tig = lane & 3;
    float rw = rw_p[0];
    float cw = 1.f - rw;
    const float* src = g_flag ? hs : (const float*)g_hsb;
    const float* Tg = g_T + ((size_t)b * SS + s0) * RR;
    const float* Vg = g_V + (size_t)b * RR * HH + k0;

#pragma unroll
    for (int j = 0; j < 8; j++) {
        int lin = tid + j * 128;
        int r = lin >> 4, c = (lin & 15) << 2;
        float4 t = *reinterpret_cast<const float4*>(Tg + (size_t)r * RR + c);
        *reinterpret_cast<float2*>(&Ts[r][c])     = make_float2(t.x, t.y);
        *reinterpret_cast<float2*>(&Ts[r][c + 2]) = make_float2(t.z, t.w);
        *reinterpret_cast<float4*>(&Vs[r][c]) =
            *reinterpret_cast<const float4*>(Vg + (size_t)r * HH + c);
    }
    __syncthreads();

    float4 afr[8];
#pragma unroll
    for (int ks = 0; ks < 8; ks++) {
        int kk = ks * 8;
        afr[ks].x = Ts[warp * 16 + gid    ][kk + tig];
        afr[ks].y = Ts[warp * 16 + gid + 8][kk + tig];
        afr[ks].z = Ts[warp * 16 + gid    ][kk + tig + 4];
        afr[ks].w = Ts[warp * 16 + gid + 8][kk + tig + 4];
    }

    // prefetch V tile 1 into registers while computing tile 0
    float4 vpf[8];
#pragma unroll
    for (int j = 0; j < 8; j++) {
        int lin = tid + j * 128;
        int r = lin >> 4, c = (lin & 15) << 2;
        vpf[j] = *reinterpret_cast<const float4*>(Vg + 64 + (size_t)r * HH + c);
    }

#pragma unroll 1
    for (int tile = 0; tile < 2; tile++) {
        if (tile) {
            __syncthreads();
#pragma unroll
            for (int j = 0; j < 8; j++) {
                int lin = tid + j * 128;
                int r = lin >> 4, c = (lin & 15) << 2;
                *reinterpret_cast<float4*>(&Vs[r][c]) = vpf[j];
            }
            __syncthreads();
        }
        float acc[8][4] = {};
#pragma unroll
        for (int ks = 0; ks < 8; ks++) {
            int kk = ks * 8;
            uint32_t a0 = __float_as_uint(afr[ks].x);
            uint32_t a1 = __float_as_uint(afr[ks].y);
            uint32_t a2 = __float_as_uint(afr[ks].z);
            uint32_t a3 = __float_as_uint(afr[ks].w);
#pragma unroll
            for (int nt = 0; nt < 8; nt++) {
                uint32_t b0 = __float_as_uint(Vs[kk + tig    ][nt * 8 + gid]);
                uint32_t b1 = __float_as_uint(Vs[kk + tig + 4][nt * 8 + gid]);
                mma_tf32(acc[nt], a0, a1, a2, a3, b0, b1);
            }
        }
        size_t rowA = ((size_t)b * SS + s0 + warp * 16 + gid    ) * HH + k0 + tile * 64;
        size_t rowB = rowA + (size_t)8 * HH;
#pragma unroll
        for (int nt = 0; nt < 8; nt++) {
            int c = nt * 8 + 2 * tig;
            float2 xa = *reinterpret_cast<const float2*>(src + rowA + c);
            float2 xb = *reinterpret_cast<const float2*>(src + rowB + c);
            float2 oa = make_float2(rw * xa.x + cw * acc[nt][0], rw * xa.y + cw * acc[nt][1]);
            float2 ob = make_float2(rw * xb.x + cw * acc[nt][2], rw * xb.y + cw * acc[nt][3]);
            *reinterpret_cast<float2*>(out + rowA + c) = oa;
            *reinterpret_cast<float2*>(out + rowB + c) = ob;
        }
    }
}

// ---------------- launch ----------------
extern "C" void kernel_launch(void* const* d_in, const int* in_sizes, int n_in,
                              void* d_out, int out_size) {
    const float* hs  = (const float*)d_in[0];
    const float* W1  = (const float*)d_in[1];
    const float* b1  = (const float*)d_in[2];
    const float* g1  = (const float*)d_in[3];
    const float* be1 = (const float*)d_in[4];
    const float* W2  = (const float*)d_in[5];
    const float* b2  = (const float*)d_in[6];
    const float* g2  = (const float*)d_in[7];
    const float* be2 = (const float*)d_in[8];
    const float* W3  = (const float*)d_in[9];
    const float* b3  = (const float*)d_in[10];
    const float* Wu  = (const float*)d_in[11];
    const float* bu  = (const float*)d_in[12];
    const float* Wv  = (const float*)d_in[13];
    const float* bv  = (const float*)d_in[14];
    const float* su  = (const float*)d_in[15];
    const float* sv  = (const float*)d_in[16];
    const float* rw  = (const float*)d_in[17];
    const float* base= (const float*)d_in[18];
    float* out = (float*)d_out;

    float *p_feats, *p_part, *p_part2, *p_h1, *p_h2;
    cudaGetSymbolAddress((void**)&p_feats, g_feats);
    cudaGetSymbolAddress((void**)&p_part,  g_partial);
    cudaGetSymbolAddress((void**)&p_part2, g_part2);
    cudaGetSymbolAddress((void**)&p_h1,    g_h1);
    cudaGetSymbolAddress((void**)&p_h2,    g_h2);

    k_moments<<<dim3(HH / 256, BB, NSPLIT), 256>>>(hs);
    k_combine_nrm<<<dim3(9, BB), 256>>>();

    // layer 1: [4,14336] @ [14336,1024], Kchunk=64 -> 224 blocks (+ idcheck tail)
    k_gemm1<<<KSPLIT1, 256>>>(W1, p_feats, p_part, base);
    k_reduce1<<<dim3(BB * N1 / 256, KRED), 256>>>(p_part, p_part2);
    k_lnr<<<BB, 256>>>(p_part2, b1, g1, be1, p_h1, N1, KRED);
    // layer 2: [4,1024] @ [1024,512]
    k_gemm_sk<<<dim3(N2 / 256, 8), 256>>>(W2, p_h1, p_part, N1, N2, 128);
    k_lnr<<<BB, 256>>>(p_part, b2, g2, be2, p_h2, N2, 8);
    // layer 3: [4,512] @ [512,256] -> partials consumed by k_uv
    k_gemm_sk<<<dim3(1, 4), 256>>>(W3, p_h2, p_part, N2, N3, 128);

    k_uv<<<dim3(HH * RR / 1024, 2), 256>>>(Wu, bu, Wv, bv, su, sv, b3, p_part);
    k_T<<<dim3(SS / 64, BB), 256>>>(hs);
    k_basegemm<<<dim3(HH / 512, SS / 64, BB), 256>>>(hs, base);
    k_final<<<dim3(HH / 128, SS / 64, BB), 128>>>(hs, rw, out);
}

// round 16
// speedup vs baseline: 1.1405x; 1.0226x over previous
#include <cuda_runtime.h>
#include <math.h>
#include <stdint.h>

#define BB 4
#define SS 4096
#define HH 2048
#define RR 64
#define K1 (HH * 7)      // 14336
#define N1 1024
#define N2 512
#define N3 256
#define NSPLIT 32
#define SCHUNK (SS / NSPLIT)   // 128 s rows per block
#define SUB 32                 // s rows per smem sub-tile
#define KSPLIT1 224            // layer-1 split-K chunks (Kchunk=64)
#define KRED 8                 // second-stage reduction width

// ---------------- scratch (__device__ globals; no allocations) ----------------
__device__ float g_p1[NSPLIT * BB * HH];
__device__ float g_p2[NSPLIT * BB * HH];
__device__ float g_p3[NSPLIT * BB * HH];
__device__ float g_p4[NSPLIT * BB * HH];
__device__ float g_pmx[NSPLIT * BB * HH];
__device__ float g_pmn[NSPLIT * BB * HH];
__device__ float g_rn2[8 * BB * SS];   // rownorm sum-of-squares partials (8 h-slices)
__device__ float g_feats[BB * K1];
__device__ float g_partial[KSPLIT1 * BB * N1];
__device__ float g_part2[KRED * BB * N1];
__device__ float g_h1[BB * N1];
__device__ float g_h2[BB * N2];
__device__ float g_U[BB * HH * RR];   // [b][h][r]  (tf32-rounded)
__device__ float g_V[BB * RR * HH];   // [b][r][h]  (tf32-rounded)
__device__ float g_T[BB * SS * RR];   // hs @ U     (tf32-rounded)
__device__ float g_hsb[(size_t)BB * SS * HH];  // hs @ base (general fallback only)
__device__ int   g_flag;              // 1 = base_transform is identity

// ---------------- tf32 mma helpers ----------------
__device__ __forceinline__ float tf32r(float x) {
    uint32_t u;
    asm("cvt.rna.tf32.f32 %0, %1;" : "=r"(u) : "f"(x));
    return __uint_as_float(u);
}
__device__ __forceinline__ void mma_tf32(float* c,
        uint32_t a0, uint32_t a1, uint32_t a2, uint32_t a3,
        uint32_t b0, uint32_t b1) {
    asm volatile(
        "mma.sync.aligned.m16n8k8.row.col.f32.tf32.tf32.f32 "
        "{%0,%1,%2,%3}, {%4,%5,%6,%7}, {%8,%9}, {%0,%1,%2,%3};"
        : "+f"(c[0]), "+f"(c[1]), "+f"(c[2]), "+f"(c[3])
        : "r"(a0), "r"(a1), "r"(a2), "r"(a3), "r"(b0), "r"(b1));
}

// ---------------- moments + rownorm, fused via smem tiles ----------------
__global__ __launch_bounds__(256) void k_moments(const float* __restrict__ hs) {
    __shared__ float tile[SUB][260];
    int h0 = blockIdx.x * 256;
    int b  = blockIdx.y;
    int sp = blockIdx.z;
    int tid = threadIdx.x;
    int warp = tid >> 5, lane = tid & 31;
    const float* base = hs + ((size_t)b * SS + (size_t)sp * SCHUNK) * HH + h0;

    float s1 = 0.f, s2 = 0.f, s3 = 0.f, s4 = 0.f;
    float mx = -1e30f, mn = 1e30f;

    float4 pf[8];
#pragma unroll
    for (int j = 0; j < 8; j++) {
        int lin = tid + j * 256;
        int r = lin >> 6, c = (lin & 63) << 2;
        pf[j] = *reinterpret_cast<const float4*>(base + (size_t)r * HH + c);
    }

#pragma unroll 1
    for (int st = 0; st < 4; st++) {
        if (st) __syncthreads();
#pragma unroll
        for (int j = 0; j < 8; j++) {
            int lin = tid + j * 256;
            int r = lin >> 6, c = (lin & 63) << 2;
            *reinterpret_cast<float4*>(&tile[r][c]) = pf[j];
        }
        __syncthreads();
        if (st < 3) {
#pragma unroll
            for (int j = 0; j < 8; j++) {
                int lin = tid + j * 256;
                int r = lin >> 6, c = (lin & 63) << 2;
                pf[j] = *reinterpret_cast<const float4*>(
                    base + (size_t)((st + 1) * SUB + r) * HH + c);
            }
        }
#pragma unroll
        for (int s = 0; s < SUB; s++) {
            float x  = tile[s][tid];
            float x2 = x * x;
            s1 += x; s2 += x2; s3 += x2 * x; s4 += x2 * x2;
            mx = fmaxf(mx, x); mn = fminf(mn, x);
        }
#pragma unroll
        for (int i = 0; i < 4; i++) {
            int r = warp * 4 + i;
            float4 a  = *reinterpret_cast<const float4*>(&tile[r][lane * 4]);
            float4 bq = *reinterpret_cast<const float4*>(&tile[r][lane * 4 + 128]);
            float v = (a.x * a.x + a.y * a.y) + (a.z * a.z + a.w * a.w)
                    + (bq.x * bq.x + bq.y * bq.y) + (bq.z * bq.z + bq.w * bq.w);
#pragma unroll
            for (int o = 16; o > 0; o >>= 1) v += __shfl_xor_sync(0xffffffffu, v, o);
            if (lane == 0)
                g_rn2[blockIdx.x * (BB * SS) + b * SS + sp * SCHUNK + st * SUB + r] = v;
        }
    }
    int idx = (sp * BB + b) * HH + h0 + tid;
    g_p1[idx] = s1; g_p2[idx] = s2; g_p3[idx] = s3; g_p4[idx] = s4;
    g_pmx[idx] = mx; g_pmn[idx] = mn;
    if (blockIdx.x == 0 && blockIdx.y == 0 && blockIdx.z == 0 && tid == 0)
        g_flag = 1;   // reset identity flag; checked by k_gemm1 (later in stream)
}

// combine chunk partials -> features; blockIdx.x==8 lane does the rownorm mean
__global__ void k_combine_nrm() {
    int b = blockIdx.y;
    if (blockIdx.x == 8) {
        float acc = 0.f;
        for (int i = threadIdx.x; i < SS; i += 256) {
            float v = 0.f;
#pragma unroll
            for (int hsl = 0; hsl < 8; hsl++) v += g_rn2[hsl * (BB * SS) + b * SS + i];
            acc += sqrtf(v);
        }
        __shared__ float sh[256];
        __shared__ float nrm;
        sh[threadIdx.x] = acc; __syncthreads();
        for (int o = 128; o > 0; o >>= 1) {
            if (threadIdx.x < o) sh[threadIdx.x] += sh[threadIdx.x + o];
            __syncthreads();
        }
        if (threadIdx.x == 0) nrm = sh[0] / (float)SS;
        __syncthreads();
        for (int h = threadIdx.x; h < HH; h += 256)
            g_feats[(size_t)b * K1 + 2 * HH + h] = nrm;
        return;
    }
    int h = blockIdx.x * 256 + threadIdx.x;
    float s1 = 0.f, s2 = 0.f, s3 = 0.f, s4 = 0.f;
    float mx = -1e30f, mn = 1e30f;
#pragma unroll
    for (int sp = 0; sp < NSPLIT; sp++) {
        int idx = (sp * BB + b) * HH + h;
        s1 += g_p1[idx]; s2 += g_p2[idx]; s3 += g_p3[idx]; s4 += g_p4[idx];
        mx = fmaxf(mx, g_pmx[idx]); mn = fminf(mn, g_pmn[idx]);
    }
    float n  = (float)SS;
    float mu = s1 / n;
    float e2 = s2 / n;
    float e3 = s3 / n;
    float e4 = s4 / n;
    float varu = (s2 - n * mu * mu) / (n - 1.f);
    if (varu < 0.f) varu = 0.f;
    float sd  = sqrtf(varu);
    float m3  = e3 - 3.f * mu * e2 + 2.f * mu * mu * mu;
    float m4  = e4 - 4.f * mu * e3 + 6.f * mu * mu * e2 - 3.f * mu * mu * mu * mu;
    float skew = m3 / (sd * sd * sd + 1e-8f);
    float kurt = m4 / (varu * varu + 1e-8f) - 3.f;
    float* f = g_feats + (size_t)b * K1;
    f[0 * HH + h] = mu;
    f[1 * HH + h] = sd;
    f[3 * HH + h] = mx;
    f[4 * HH + h] = mn;
    f[5 * HH + h] = skew;
    f[6 * HH + h] = kurt;
}

// ---------------- layer-1 GEMM: Kchunk=64, float4 over full N, + idcheck tail ----------------
__global__ __launch_bounds__(256) void k_gemm1(const float* __restrict__ W,
        const float* __restrict__ X, float* __restrict__ partial,
        const float* __restrict__ base) {
    __shared__ float xs[BB][64];
    int tid = threadIdx.x;
    int k0 = blockIdx.x * 64;
    xs[tid >> 6][tid & 63] = X[(size_t)(tid >> 6) * K1 + k0 + (tid & 63)];
    __syncthreads();
    int n4 = tid * 4;
    float4 acc[BB];
#pragma unroll
    for (int bq = 0; bq < BB; bq++) acc[bq] = make_float4(0.f, 0.f, 0.f, 0.f);
    const float* Wp = W + (size_t)k0 * N1 + n4;
#pragma unroll 8
    for (int kk = 0; kk < 64; kk++) {
        float4 w = *reinterpret_cast<const float4*>(Wp + (size_t)kk * N1);
#pragma unroll
        for (int bq = 0; bq < BB; bq++) {
            float h = xs[bq][kk];
            acc[bq].x += h * w.x; acc[bq].y += h * w.y;
            acc[bq].z += h * w.z; acc[bq].w += h * w.w;
        }
    }
    int p = blockIdx.x * BB;
#pragma unroll
    for (int bq = 0; bq < BB; bq++)
        *reinterpret_cast<float4*>(partial + (size_t)(p + bq) * N1 + n4) = acc[bq];

    // identity check of base_transform (flag was reset by k_moments, stream-ordered)
    int gtid = blockIdx.x * 256 + tid;
    bool bad = false;
    for (int i4 = gtid; i4 < HH * HH / 4; i4 += KSPLIT1 * 256) {
        int e0 = i4 * 4;
        int r = e0 >> 11, c0 = e0 & 2047;
        float4 x = *reinterpret_cast<const float4*>(base + e0);
        float4 e;
        e.x = (r == c0 + 0) ? 1.f : 0.f;
        e.y = (r == c0 + 1) ? 1.f : 0.f;
        e.z = (r == c0 + 2) ? 1.f : 0.f;
        e.w = (r == c0 + 3) ? 1.f : 0.f;
        if (x.x != e.x || x.y != e.y || x.z != e.z || x.w != e.w) bad = true;
    }
    if (bad) g_flag = 0;
}

// ---------------- stage-1 reduce: 224 partials -> 8, parallel over ks groups ----------------
__global__ __launch_bounds__(256) void k_reduce1(const float* __restrict__ partial,
        float* __restrict__ part2) {
    int i   = blockIdx.x * 256 + threadIdx.x;   // flat (b,n)
    int ksg = blockIdx.y;
    const int GRP = KSPLIT1 / KRED;             // 28
    float a = 0.f;
    const float* p = partial + (size_t)(ksg * GRP * BB) * N1 + i;
#pragma unroll 7
    for (int ks = 0; ks < GRP; ks++)
        a += p[(size_t)ks * BB * N1];
    part2[(size_t)ksg * BB * N1 + i] = a;
}

// ---------------- fused ksplit-reduce + bias + LayerNorm + ReLU ----------------
__global__ __launch_bounds__(256) void k_lnr(const float* __restrict__ partial,
        const float* __restrict__ bias, const float* __restrict__ g,
        const float* __restrict__ beta, float* __restrict__ out, int N, int ksplit) {
    int b = blockIdx.x, t = threadIdx.x;
    int nper = N >> 8;   // 4 (N1) or 2 (N2)
    float a[4];
    float s = 0.f, s2 = 0.f;
    for (int j = 0; j < nper; j++) {
        int n = t + j * 256;
        float v = bias[n];
        for (int ks = 0; ks < ksplit; ks++)
            v += partial[(size_t)(ks * BB + b) * N + n];
        a[j] = v;
        s += v; s2 += v * v;
    }
    __shared__ float sha[256];
    __shared__ float shb[256];
    __shared__ float s_mean, s_rstd;
    sha[t] = s; shb[t] = s2; __syncthreads();
    for (int o = 128; o > 0; o >>= 1) {
        if (t < o) { sha[t] += sha[t + o]; shb[t] += shb[t + o]; }
        __syncthreads();
    }
    if (t == 0) {
        float mean = sha[0] / (float)N;
        float var  = shb[0] / (float)N - mean * mean;
        s_mean = mean;
        s_rstd = rsqrtf(var + 1e-5f);
    }
    __syncthreads();
    float mean = s_mean, rstd = s_rstd;
    for (int j = 0; j < nper; j++) {
        int n = t + j * 256;
        out[(size_t)b * N + n] = fmaxf((a[j] - mean) * rstd * g[n] + beta[n], 0.f);
    }
}

// ---------------- small-M GEMM (M=4) with split-K (layers 2,3) ----------------
__global__ void k_gemm_sk(const float* __restrict__ W, const float* __restrict__ X,
                          float* __restrict__ partial, int K, int N, int Kchunk) {
    __shared__ float xs[BB][128];
    int n  = blockIdx.x * 256 + threadIdx.x;
    int k0 = blockIdx.y * Kchunk;
    for (int b = 0; b < BB; b++)
        for (int i = threadIdx.x; i < Kchunk; i += 256)
            xs[b][i] = X[(size_t)b * K + k0 + i];
    __syncthreads();
    if (n >= N) return;
    float a0 = 0.f, a1 = 0.f, a2 = 0.f, a3 = 0.f;
    const float* Wp = W + (size_t)k0 * N + n;
#pragma unroll 8
    for (int kk = 0; kk < Kchunk; kk++) {
        float w = Wp[(size_t)kk * N];
        a0 += xs[0][kk] * w; a1 += xs[1][kk] * w;
        a2 += xs[2][kk] * w; a3 += xs[3][kk] * w;
    }
    int p = blockIdx.y * BB;
    partial[(size_t)(p + 0) * N + n] = a0;
    partial[(size_t)(p + 1) * N + n] = a1;
    partial[(size_t)(p + 2) * N + n] = a2;
    partial[(size_t)(p + 3) * N + n] = a3;
}

// U/V heads. h3 recomputed in-block from layer-3 split-K partials (+bias,ReLU).
__global__ __launch_bounds__(256) void k_uv(const float* __restrict__ Wu,
        const float* __restrict__ bu, const float* __restrict__ Wv,
        const float* __restrict__ bv, const float* __restrict__ su,
        const float* __restrict__ sv, const float* __restrict__ b3,
        const float* __restrict__ part3) {
    const int NU = HH * RR;
    int isv = blockIdx.y;
    const float* W    = isv ? Wv : Wu;
    const float* bias = isv ? bv : bu;
    float scale       = isv ? sv[0] : su[0];
    float* outp       = isv ? g_V : g_U;
    __shared__ float hsh[BB][N3];
    for (int i = threadIdx.x; i < BB * N3; i += 256) {
        int bq = i >> 8, nn = i & 255;
        float a = b3[nn];
#pragma unroll
        for (int ks = 0; ks < 4; ks++)
            a += part3[(size_t)(ks * BB + bq) * N3 + nn];
        hsh[bq][nn] = fmaxf(a, 0.f);
    }
    __syncthreads();
    int n = (blockIdx.x * 256 + threadIdx.x) * 4;
    float4 acc[BB];
#pragma unroll
    for (int bq = 0; bq < BB; bq++) acc[bq] = make_float4(0.f, 0.f, 0.f, 0.f);
    const float* Wp = W + n;
#pragma unroll 8
    for (int k = 0; k < N3; k++) {
        float4 w = *reinterpret_cast<const float4*>(Wp + (size_t)k * NU);
#pragma unroll
        for (int bq = 0; bq < BB; bq++) {
            float h = hsh[bq][k];
            acc[bq].x += h * w.x; acc[bq].y += h * w.y;
            acc[bq].z += h * w.z; acc[bq].w += h * w.w;
        }
    }
    float4 bb4 = *reinterpret_cast<const float4*>(bias + n);
#pragma unroll
    for (int bq = 0; bq < BB; bq++) {
        float4 o;
        o.x = tf32r((acc[bq].x + bb4.x) * scale);
        o.y = tf32r((acc[bq].y + bb4.y) * scale);
        o.z = tf32r((acc[bq].z + bb4.z) * scale);
        o.w = tf32r((acc[bq].w + bb4.w) * scale);
        *reinterpret_cast<float4*>(outp + (size_t)bq * NU + n) = o;
    }
}

// ---------------- T[b,s,r] = sum_h hs[b,s,h]*U[b,h,r]  (tf32 tensor cores) ----------------
__global__ __launch_bounds__(256) void k_T(const float* __restrict__ hs) {
    __shared__ float As[64][36];
    __shared__ float Us[32][72];
    int b   = blockIdx.y;
    int s0  = blockIdx.x * 64;
    int tid = threadIdx.x;
    int warp = tid >> 5, lane = tid & 31;
    int gid = lane >> 2, tig = lane & 3;
    int wm = warp & 3, wn = warp >> 2;
    const float* A = hs  + ((size_t)b * SS + s0) * HH;
    const float* U = g_U + (size_t)b * HH * RR;

    int laR[2], laC[2], luR[2], luC[2];
#pragma unroll
    for (int j = 0; j < 2; j++) {
        int lin = tid + j * 256;
        laR[j] = lin >> 3;  laC[j] = (lin & 7)  << 2;   // A: 64 x 32
        luR[j] = lin >> 4;  luC[j] = (lin & 15) << 2;   // U: 32 x 64
    }
    float4 fa[2], fu[2];
#pragma unroll
    for (int j = 0; j < 2; j++) {
        fa[j] = *reinterpret_cast<const float4*>(A + (size_t)laR[j] * HH + laC[j]);
        fu[j] = *reinterpret_cast<const float4*>(U + (size_t)luR[j] * RR + luC[j]);
    }

    float acc[4][4] = {};
    for (int h0 = 0; h0 < HH; h0 += 32) {
        if (h0) __syncthreads();
#pragma unroll
        for (int j = 0; j < 2; j++) {
            float* pA = &As[laR[j]][laC[j]];
            pA[0] = tf32r(fa[j].x); pA[1] = tf32r(fa[j].y);
            pA[2] = tf32r(fa[j].z); pA[3] = tf32r(fa[j].w);
            *reinterpret_cast<float2*>(&Us[luR[j]][luC[j]])     = make_float2(fu[j].x, fu[j].y);
            *reinterpret_cast<float2*>(&Us[luR[j]][luC[j] + 2]) = make_float2(fu[j].z, fu[j].w);
        }
        __syncthreads();
        if (h0 + 32 < HH) {
#pragma unroll
            for (int j = 0; j < 2; j++) {
                fa[j] = *reinterpret_cast<const float4*>(A + (size_t)laR[j] * HH + h0 + 32 + laC[j]);
                fu[j] = *reinterpret_cast<const float4*>(U + (size_t)(h0 + 32 + luR[j]) * RR + luC[j]);
            }
        }
#pragma unroll
        for (int ks = 0; ks < 4; ks++) {
            int kk = ks * 8;
            uint32_t a0 = __float_as_uint(As[wm * 16 + gid    ][kk + tig]);
            uint32_t a1 = __float_as_uint(As[wm * 16 + gid + 8][kk + tig]);
            uint32_t a2 = __float_as_uint(As[wm * 16 + gid    ][kk + tig + 4]);
            uint32_t a3 = __float_as_uint(As[wm * 16 + gid + 8][kk + tig + 4]);
#pragma unroll
            for (int nt = 0; nt < 4; nt++) {
                int nc = wn * 32 + nt * 8 + gid;
                uint32_t b0 = __float_as_uint(Us[kk + tig    ][nc]);
                uint32_t b1 = __float_as_uint(Us[kk + tig + 4][nc]);
                mma_tf32(acc[nt], a0, a1, a2, a3, b0, b1);
            }
        }
    }
    float* T = g_T + ((size_t)b * SS + s0 + wm * 16) * RR + wn * 32;
#pragma unroll
    for (int nt = 0; nt < 4; nt++) {
        int c = nt * 8 + 2 * tig;
        *reinterpret_cast<float2*>(T + (size_t)(gid    ) * RR + c) =
            make_float2(tf32r(acc[nt][0]), tf32r(acc[nt][1]));
        *reinterpret_cast<float2*>(T + (size_t)(gid + 8) * RR + c) =
            make_float2(tf32r(acc[nt][2]), tf32r(acc[nt][3]));
    }
}

// fallback: g_hsb = hs @ base (only when base != I; early-exits otherwise). 8 k-tiles/block.
__global__ void k_basegemm(const float* __restrict__ hs, const float* __restrict__ base) {
    if (g_flag) return;
    __shared__ float As2[64][17];
    __shared__ float Bs2[16][64];
    int b   = blockIdx.z;
    int s0  = blockIdx.y * 64;
    int tid = threadIdx.x, tx = tid % 16, ty = tid / 16;
    const float* A = hs + ((size_t)b * SS + s0) * HH;
    for (int kt = 0; kt < 8; kt++) {
        int k0t = (blockIdx.x * 8 + kt) * 64;
        float acc[4][4] = {};
        for (int h0 = 0; h0 < HH; h0 += 16) {
#pragma unroll
            for (int j = 0; j < 4; j++) {
                int idx = tid + j * 256, r = idx / 16, c = idx % 16;
                As2[r][c] = A[(size_t)r * HH + h0 + c];
            }
#pragma unroll
            for (int j = 0; j < 4; j++) {
                int idx = tid + j * 256, r = idx / 64, c = idx % 64;
                Bs2[r][c] = base[(size_t)(h0 + r) * HH + k0t + c];
            }
            __syncthreads();
#pragma unroll
            for (int kk = 0; kk < 16; kk++) {
                float af[4], bf[4];
#pragma unroll
                for (int i = 0; i < 4; i++) af[i] = As2[ty * 4 + i][kk];
#pragma unroll
                for (int j = 0; j < 4; j++) bf[j] = Bs2[kk][tx * 4 + j];
#pragma unroll
                for (int i = 0; i < 4; i++)
#pragma unroll
                    for (int j = 0; j < 4; j++) acc[i][j] += af[i] * bf[j];
            }
            __syncthreads();
        }
        float* Op = g_hsb + ((size_t)b * SS + s0) * HH + k0t;
#pragma unroll
        for (int i = 0; i < 4; i++) {
            float4 v = make_float4(acc[i][0], acc[i][1], acc[i][2], acc[i][3]);
            *reinterpret_cast<float4*>(Op + (size_t)(ty * 4 + i) * HH + tx * 4) = v;
        }
    }
}

// ---------------- out = rw*src + (1-rw)*T@V ----------------
// tf32, 2 k-tiles/block, V prefetch. Warps 2M x 2N; each warp covers 32 rows as
// two m16 sub-tiles reusing every B-fragment twice (LDS:MMA 1:1 instead of 2:1).
__global__ __launch_bounds__(128) void k_final(const float* __restrict__ hs,
                                               const float* __restrict__ rw_p,
                                               float* __restrict__ out) {
    __shared__ float Ts[64][68];
    __shared__ float Vs[64][72];
    int b  = blockIdx.z;
    int s0 = blockIdx.y * 64;
    int k0 = blockIdx.x * 128;
    int tid = threadIdx.x;
    int warp = tid >> 5, lane = tid & 31;
    int gid = lane >> 2, tig = lane & 3;
    int wm = warp >> 1, wn = warp & 1;   // 2M x 2N warp grid
    float rw = rw_p[0];
    float cw = 1.f - rw;
    const float* src = g_flag ? hs : (const float*)g_hsb;
    const float* Tg = g_T + ((size_t)b * SS + s0) * RR;
    const float* Vg = g_V + (size_t)b * RR * HH + k0;

#pragma unroll
    for (int j = 0; j < 8; j++) {
        int lin = tid + j * 128;
        int r = lin >> 4, c = (lin & 15) << 2;
        float4 t = *reinterpret_cast<const float4*>(Tg + (size_t)r * RR + c);
        *reinterpret_cast<float2*>(&Ts[r][c])     = make_float2(t.x, t.y);
        *reinterpret_cast<float2*>(&Ts[r][c + 2]) = make_float2(t.z, t.w);
        *reinterpret_cast<float4*>(&Vs[r][c]) =
            *reinterpret_cast<const float4*>(Vg + (size_t)r * HH + c);
    }
    __syncthreads();

    // A-fragments: 2 m16 sub-tiles x 8 ks, register-resident
    float4 afr[2][8];
#pragma unroll
    for (int ms = 0; ms < 2; ms++) {
        int row = wm * 32 + ms * 16;
#pragma unroll
        for (int ks = 0; ks < 8; ks++) {
            int kk = ks * 8;
            afr[ms][ks].x = Ts[row + gid    ][kk + tig];
            afr[ms][ks].y = Ts[row + gid + 8][kk + tig];
            afr[ms][ks].z = Ts[row + gid    ][kk + tig + 4];
            afr[ms][ks].w = Ts[row + gid + 8][kk + tig + 4];
        }
    }

    // prefetch V tile 1 into registers while computing tile 0
    float4 vpf[8];
#pragma unroll
    for (int j = 0; j < 8; j++) {
        int lin = tid + j * 128;
        int r = lin >> 4, c = (lin & 15) << 2;
        vpf[j] = *reinterpret_cast<const float4*>(Vg + 64 + (size_t)r * HH + c);
    }

#pragma unroll 1
    for (int tile = 0; tile < 2; tile++) {
        if (tile) {
            __syncthreads();   // all warps done reading Vs(tile 0)
#pragma unroll
            for (int j = 0; j < 8; j++) {
                int lin = tid + j * 128;
                int r = lin >> 4, c = (lin & 15) << 2;
                *reinterpret_cast<float4*>(&Vs[r][c]) = vpf[j];
            }
            __syncthreads();
        }
        float acc[2][4][4] = {};
#pragma unroll
        for (int ks = 0; ks < 8; ks++) {
            int kk = ks * 8;
#pragma unroll
            for (int nt = 0; nt < 4; nt++) {
                int nc = wn * 32 + nt * 8 + gid;
                uint32_t b0 = __float_as_uint(Vs[kk + tig    ][nc]);
                uint32_t b1 = __float_as_uint(Vs[kk + tig + 4][nc]);
                mma_tf32(acc[0][nt],
                         __float_as_uint(afr[0][ks].x), __float_as_uint(afr[0][ks].y),
                         __float_as_uint(afr[0][ks].z), __float_as_uint(afr[0][ks].w),
                         b0, b1);
                mma_tf32(acc[1][nt],
                         __float_as_uint(afr[1][ks].x), __float_as_uint(afr[1][ks].y),
                         __float_as_uint(afr[1][ks].z), __float_as_uint(afr[1][ks].w),
                         b0, b1);
            }
        }
#pragma unroll
        for (int ms = 0; ms < 2; ms++) {
            size_t rowA = ((size_t)b * SS + s0 + wm * 32 + ms * 16 + gid) * HH
                        + k0 + tile * 64 + wn * 32;
            size_t rowB = rowA + (size_t)8 * HH;
#pragma unroll
            for (int nt = 0; nt < 4; nt++) {
                int c = nt * 8 + 2 * tig;
                float2 xa = *reinterpret_cast<const float2*>(src + rowA + c);
                float2 xb = *reinterpret_cast<const float2*>(src + rowB + c);
                float2 oa = make_float2(rw * xa.x + cw * acc[ms][nt][0],
                                        rw * xa.y + cw * acc[ms][nt][1]);
                float2 ob = make_float2(rw * xb.x + cw * acc[ms][nt][2],
                                        rw * xb.y + cw * acc[ms][nt][3]);
                *reinterpret_cast<float2*>(out + rowA + c) = oa;
                *reinterpret_cast<float2*>(out + rowB + c) = ob;
            }
        }
    }
}

// ---------------- launch ----------------
extern "C" void kernel_launch(void* const* d_in, const int* in_sizes, int n_in,
                              void* d_out, int out_size) {
    const float* hs  = (const float*)d_in[0];
    const float* W1  = (const float*)d_in[1];
    const float* b1  = (const float*)d_in[2];
    const float* g1  = (const float*)d_in[3];
    const float* be1 = (const float*)d_in[4];
    const float* W2  = (const float*)d_in[5];
    const float* b2  = (const float*)d_in[6];
    const float* g2  = (const float*)d_in[7];
    const float* be2 = (const float*)d_in[8];
    const float* W3  = (const float*)d_in[9];
    const float* b3  = (const float*)d_in[10];
    const float* Wu  = (const float*)d_in[11];
    const float* bu  = (const float*)d_in[12];
    const float* Wv  = (const float*)d_in[13];
    const float* bv  = (const float*)d_in[14];
    const float* su  = (const float*)d_in[15];
    const float* sv  = (const float*)d_in[16];
    const float* rw  = (const float*)d_in[17];
    const float* base= (const float*)d_in[18];
    float* out = (float*)d_out;

    float *p_feats, *p_part, *p_part2, *p_h1, *p_h2;
    cudaGetSymbolAddress((void**)&p_feats, g_feats);
    cudaGetSymbolAddress((void**)&p_part,  g_partial);
    cudaGetSymbolAddress((void**)&p_part2, g_part2);
    cudaGetSymbolAddress((void**)&p_h1,    g_h1);
    cudaGetSymbolAddress((void**)&p_h2,    g_h2);

    k_moments<<<dim3(HH / 256, BB, NSPLIT), 256>>>(hs);
    k_combine_nrm<<<dim3(9, BB), 256>>>();

    // layer 1: [4,14336] @ [14336,1024], Kchunk=64 -> 224 blocks (+ idcheck tail)
    k_gemm1<<<KSPLIT1, 256>>>(W1, p_feats, p_part, base);
    k_reduce1<<<dim3(BB * N1 / 256, KRED), 256>>>(p_part, p_part2);
    k_lnr<<<BB, 256>>>(p_part2, b1, g1, be1, p_h1, N1, KRED);
    // layer 2: [4,1024] @ [1024,512]
    k_gemm_sk<<<dim3(N2 / 256, 8), 256>>>(W2, p_h1, p_part, N1, N2, 128);
    k_lnr<<<BB, 256>>>(p_part, b2, g2, be2, p_h2, N2, 8);
    // layer 3: [4,512] @ [512,256] -> partials consumed by k_uv
    k_gemm_sk<<<dim3(1, 4), 256>>>(W3, p_h2, p_part, N2, N3, 128);

    k_uv<<<dim3(HH * RR / 1024, 2), 256>>>(Wu, bu, Wv, bv, su, sv, b3, p_part);
    k_T<<<dim3(SS / 64, BB), 256>>>(hs);
    k_basegemm<<<dim3(HH / 512, SS / 64, BB), 256>>>(hs, base);
    k_final<<<dim3(HH / 128, SS / 64, BB), 128>>>(hs, rw, out);
}